// round 4
// baseline (speedup 1.0000x reference)
#include <cuda_runtime.h>
#include <cuda_bf16.h>

// ---------------------------------------------------------------------------
// EGNN / SpatialNCA step.  N=50000 nodes, D=64, E=800000 edges, P=2.
//
// Inputs (metadata order):
//  0 h[N,64] 1 pos[N,2] 2 h_init[N,64]
//  3 W_msg1[129,64] 4 b_msg1[64] 5 W_msg2[64,64] 6 b_msg2[64]
//  7 W_pos1[64,64]  8 b_pos1[64] 9 W_pos2[64,1] 10 b_pos2[1]
// 11 W_h1[128,64]  12 b_h1[64]  13 W_h2[64,64]  14 b_h2[64]
// 15 edge_index[2,E]  (int32 OR int64 — detected at runtime)
// Output: [N*64 h_new][N*2 pos_new] float32.
// ---------------------------------------------------------------------------

typedef unsigned long long ull;

#define MAXN 50000
#define MAXD 64
#define MAXE 800000

// scratch (device globals: allocation-free rule)
__device__ __align__(16) float d_hsum[MAXN * MAXD];
__device__ __align__(16) float d_agg[MAXN * MAXD];
__device__ __align__(16) float d_posacc[MAXN * 2];
__device__ float d_deg[MAXN];
__device__ int   d_src[MAXE];
__device__ int   d_dst[MAXE];
__device__ int   d_e32flag;   // 1 if edge_index buffer is int32, 0 if int64

// ---- packed f32x2 helpers (Blackwell-only PTX) ----------------------------
__device__ __forceinline__ ull pk2(float lo, float hi) {
    ull r;
    asm("mov.b64 %0, {%1,%2};" : "=l"(r) : "f"(lo), "f"(hi));
    return r;
}
__device__ __forceinline__ void upk2(ull v, float& lo, float& hi) {
    asm("mov.b64 {%0,%1}, %2;" : "=f"(lo), "=f"(hi) : "l"(v));
}
__device__ __forceinline__ ull fma2(ull a, ull b, ull c) {
    ull d;
    asm("fma.rn.f32x2 %0, %1, %2, %3;" : "=l"(d) : "l"(a), "l"(b), "l"(c));
    return d;
}
__device__ __forceinline__ float silu_f(float x) {
    return x / (1.0f + __expf(-x));
}

// ---- edge kernel smem layout (floats) -------------------------------------
constexpr int S_W1  = 0;                  // 129*64 = 8256
constexpr int S_W2  = S_W1 + 8256;        // 4096
constexpr int S_WP1 = S_W2 + 4096;        // 4096
constexpr int S_WP2 = S_WP1 + 4096;       // 64
constexpr int S_B1  = S_WP2 + 64;         // 64
constexpr int S_B2  = S_B1 + 64;          // 64
constexpr int S_BP1 = S_B2 + 64;          // 64
constexpr int S_BP2 = S_BP1 + 64;         // 4 (padded)
// tiles (32 edges)
constexpr int S_MIN = S_BP2 + 4;          // 32*132 = 4224 (m_in, stride 132)
constexpr int S_T1  = S_MIN + 4224;       // 32*68  = 2176 (t1 / reused as t2)
constexpr int S_M   = S_T1 + 2176;        // 32*68  = 2176 (m)
constexpr int S_REL = S_M + 2176;         // 64
constexpr int S_WE  = S_REL + 64;         // 32
constexpr int S_IDX = S_WE + 32;          // 64 ints (src[32], dst[32])
constexpr int EDGE_SMEM_BYTES = (S_IDX + 64) * 4;   // ~101.8 KB -> 2 blocks/SM

// ---- node kernel smem layout ----------------------------------------------
constexpr int NS_WH1 = 0;                 // 128*64 = 8192
constexpr int NS_WH2 = 8192;              // 4096
constexpr int NS_BH1 = 12288;             // 64
constexpr int NS_BH2 = 12352;             // 64
constexpr int NS_X   = 12416;             // 4*128
constexpr int NS_Y   = 12928;             // 4*64
constexpr int NODE_SMEM_BYTES = (NS_Y + 256) * 4;   // ~52.7 KB -> 4 blocks/SM

// ---------------------------------------------------------------------------
// Register-tiled smem GEMM: C[32][64] = act(A[32][KD] @ W[KD][64] + b)
// 128 threads; thread computes 4 edges x 4 outputs with packed f32x2 FMAs.
// ---------------------------------------------------------------------------
template <int KD, bool DOSILU>
__device__ __forceinline__ void gemm_tile(const float* __restrict__ sA, const int ldA,
                                          const float* __restrict__ sW,
                                          const float* __restrict__ sb,
                                          float* __restrict__ sC, const int ldC,
                                          const int tid)
{
    const int tk = tid & 15;
    const int te = tid >> 4;
    const int k0 = tk << 2;   // 0..60
    const int e0 = te << 2;   // 0..28

    ull acc[4][2];
#pragma unroll
    for (int j = 0; j < 4; ++j) { acc[j][0] = 0ULL; acc[j][1] = 0ULL; }

#pragma unroll 4
    for (int i = 0; i + 1 < KD; i += 2) {
        const ulonglong2 b0 = *reinterpret_cast<const ulonglong2*>(sW + i * 64 + k0);
        const ulonglong2 b1 = *reinterpret_cast<const ulonglong2*>(sW + (i + 1) * 64 + k0);
#pragma unroll
        for (int j = 0; j < 4; ++j) {
            const float2 a = *reinterpret_cast<const float2*>(sA + (e0 + j) * ldA + i);
            const ull a0 = pk2(a.x, a.x);
            const ull a1 = pk2(a.y, a.y);
            acc[j][0] = fma2(a0, b0.x, acc[j][0]);
            acc[j][1] = fma2(a0, b0.y, acc[j][1]);
            acc[j][0] = fma2(a1, b1.x, acc[j][0]);
            acc[j][1] = fma2(a1, b1.y, acc[j][1]);
        }
    }
    if (KD & 1) {
        const int i = KD - 1;
        const ulonglong2 b0 = *reinterpret_cast<const ulonglong2*>(sW + i * 64 + k0);
#pragma unroll
        for (int j = 0; j < 4; ++j) {
            const float a = sA[(e0 + j) * ldA + i];
            const ull a0 = pk2(a, a);
            acc[j][0] = fma2(a0, b0.x, acc[j][0]);
            acc[j][1] = fma2(a0, b0.y, acc[j][1]);
        }
    }

    const float bb0 = sb[k0], bb1 = sb[k0 + 1], bb2 = sb[k0 + 2], bb3 = sb[k0 + 3];
#pragma unroll
    for (int j = 0; j < 4; ++j) {
        float r0, r1, r2, r3;
        upk2(acc[j][0], r0, r1);
        upk2(acc[j][1], r2, r3);
        r0 += bb0; r1 += bb1; r2 += bb2; r3 += bb3;
        if (DOSILU) {
            r0 = silu_f(r0); r1 = silu_f(r1);
            r2 = silu_f(r2); r3 = silu_f(r3);
        }
        const float4 v = make_float4(r0, r1, r2, r3);
        *reinterpret_cast<float4*>(sC + (e0 + j) * ldC + k0) = v;
    }
}

// ---------------------------------------------------------------------------
// Kernel 0a: detect edge_index dtype. Genuine int64 node ids are < 2^31;
// int32 data reinterpreted as int64 packs two random ids -> almost surely
// >= 2^32 within the first 1024 entries.
// ---------------------------------------------------------------------------
__global__ void egnn_detect_kernel(const long long* __restrict__ ei, const int E)
{
    __shared__ int bad;
    if (threadIdx.x == 0) bad = 0;
    __syncthreads();
    const int cnt = E < 1024 ? E : 1024;   // safe: E int64 words exist either way
    for (int i = threadIdx.x; i < cnt; i += blockDim.x) {
        const long long v = ei[i];
        if (v < 0 || v > 0x7FFFFFFFLL) bad = 1;   // benign race, same value
    }
    __syncthreads();
    if (threadIdx.x == 0) d_e32flag = bad;        // bad -> data is int32
}

// Kernel 0b: normalize indices into int scratch arrays.
__global__ void egnn_cvt_kernel(const void* __restrict__ ei, const int E)
{
    const int i = blockIdx.x * blockDim.x + threadIdx.x;
    if (i >= 2 * E) return;
    int v;
    if (d_e32flag) v = ((const int*)ei)[i];
    else           v = (int)(((const long long*)ei)[i]);
    if (i < E) d_src[i] = v;
    else       d_dst[i - E] = v;
}

// ---------------------------------------------------------------------------
// Kernel 1: hsum = h + h_init; zero accumulators.
// ---------------------------------------------------------------------------
__global__ void egnn_init_kernel(const float* __restrict__ h,
                                 const float* __restrict__ hi, const int N)
{
    const int i = blockIdx.x * blockDim.x + threadIdx.x;
    const int n4 = N * 16;  // float4 count for N*64
    if (i < n4) {
        const float4 a = reinterpret_cast<const float4*>(h)[i];
        const float4 b = reinterpret_cast<const float4*>(hi)[i];
        float4 s;
        s.x = a.x + b.x; s.y = a.y + b.y; s.z = a.z + b.z; s.w = a.w + b.w;
        reinterpret_cast<float4*>(d_hsum)[i] = s;
        reinterpret_cast<float4*>(d_agg)[i] = make_float4(0.f, 0.f, 0.f, 0.f);
    }
    if (i < N) d_deg[i] = 0.0f;
    if (i < N * 2) d_posacc[i] = 0.0f;
}

// ---------------------------------------------------------------------------
// Kernel 2: persistent edge kernel. 32-edge tiles, weights resident in smem.
// ---------------------------------------------------------------------------
__global__ void __launch_bounds__(128, 2)
egnn_edge_kernel(const float* __restrict__ pos,
                 const float* __restrict__ Wm1, const float* __restrict__ bm1,
                 const float* __restrict__ Wm2, const float* __restrict__ bm2,
                 const float* __restrict__ Wp1, const float* __restrict__ bp1,
                 const float* __restrict__ Wp2, const float* __restrict__ bp2,
                 const int E, const int N)
{
    extern __shared__ float sm[];
    const int tid = threadIdx.x;

    // stage all weights once per block
    for (int i = tid; i < 8256; i += 128) sm[S_W1 + i] = Wm1[i];
    for (int i = tid; i < 4096; i += 128) sm[S_W2 + i] = Wm2[i];
    for (int i = tid; i < 4096; i += 128) sm[S_WP1 + i] = Wp1[i];
    if (tid < 64) {
        sm[S_WP2 + tid] = Wp2[tid];
        sm[S_B1 + tid] = bm1[tid];
        sm[S_B2 + tid] = bm2[tid];
        sm[S_BP1 + tid] = bp1[tid];
    }
    if (tid == 0) sm[S_BP2] = bp2[0];
    __syncthreads();

    int* sidx = reinterpret_cast<int*>(sm + S_IDX);  // [0..31]=src, [32..63]=dst
    const int nTiles = (E + 31) >> 5;

    for (int t = blockIdx.x; t < nTiles; t += gridDim.x) {
        const int eBase = t << 5;

        if (tid < 32) {
            const int e = eBase + tid;
            int s = -1, d = -1;
            if (e < E) { s = d_src[e]; d = d_dst[e]; }
            if ((unsigned)s >= (unsigned)N) s = -1;   // safety clamp
            if ((unsigned)d >= (unsigned)N) d = -1;
            sidx[tid] = s;
            sidx[32 + tid] = d;
        }
        __syncthreads();

        // gather m_in = [h[dst](64), h[src](64), d2]; coalesced 64-float rows
        for (int idx = tid; idx < 32 * 128; idx += 128) {
            const int e = idx >> 7, c = idx & 127;
            const int node = (c < 64) ? sidx[32 + e] : sidx[e];
            float v = 0.0f;
            if (node >= 0) v = d_hsum[node * 64 + (c & 63)];
            sm[S_MIN + e * 132 + c] = v;
        }
        if (tid < 32) {
            const int s = sidx[tid], d = sidx[32 + tid];
            float r0 = 0.0f, r1 = 0.0f;
            if (s >= 0 && d >= 0) {
                r0 = pos[d * 2 + 0] - pos[s * 2 + 0];
                r1 = pos[d * 2 + 1] - pos[s * 2 + 1];
            }
            sm[S_REL + tid * 2 + 0] = r0;
            sm[S_REL + tid * 2 + 1] = r1;
            sm[S_MIN + tid * 132 + 128] = r0 * r0 + r1 * r1;
        }
        __syncthreads();

        // phi_e layer 1: t1 = silu(m_in @ W_msg1 + b_msg1)
        gemm_tile<129, true>(sm + S_MIN, 132, sm + S_W1, sm + S_B1, sm + S_T1, 68, tid);
        __syncthreads();
        // phi_e layer 2: m = silu(t1 @ W_msg2 + b_msg2)
        gemm_tile<64, true>(sm + S_T1, 68, sm + S_W2, sm + S_B2, sm + S_M, 68, tid);
        __syncthreads();
        // phi_x layer 1: t2 = silu(m @ W_pos1 + b_pos1)   (reuses T1 slot)
        gemm_tile<64, true>(sm + S_M, 68, sm + S_WP1, sm + S_BP1, sm + S_T1, 68, tid);
        __syncthreads();
        // phi_x layer 2: w = t2 @ W_pos2 + b_pos2 (scalar per edge, no silu)
        if (tid < 32) {
            float acc = sm[S_BP2];
            const float* row = sm + S_T1 + tid * 68;
#pragma unroll 8
            for (int i = 0; i < 64; ++i) acc += row[i] * sm[S_WP2 + i];
            sm[S_WE + tid] = acc;
        }
        __syncthreads();

        // scatter: agg += m, posacc += rel*w, deg += 1 (all on dst)
        for (int idx = tid; idx < 32 * 64; idx += 128) {
            const int e = idx >> 6, k = idx & 63;
            const int d = sidx[32 + e];
            if (d >= 0) atomicAdd(&d_agg[d * 64 + k], sm[S_M + e * 68 + k]);
        }
        if (tid < 32) {
            const int d = sidx[32 + tid];
            if (d >= 0) {
                const float wv = sm[S_WE + tid];
                atomicAdd(&d_posacc[d * 2 + 0], sm[S_REL + tid * 2 + 0] * wv);
                atomicAdd(&d_posacc[d * 2 + 1], sm[S_REL + tid * 2 + 1] * wv);
                atomicAdd(&d_deg[d], 1.0f);
            }
        }
        __syncthreads();
    }
}

// ---------------------------------------------------------------------------
// Kernel 3: node update (phi_h) + skip connections + pos update. Warp/node.
// ---------------------------------------------------------------------------
__global__ void __launch_bounds__(128, 4)
egnn_node_kernel(const float* __restrict__ pos,
                 const float* __restrict__ Wh1, const float* __restrict__ bh1,
                 const float* __restrict__ Wh2, const float* __restrict__ bh2,
                 float* __restrict__ out, const int N)
{
    extern __shared__ float sm[];
    const int tid = threadIdx.x;

    for (int i = tid; i < 8192; i += 128) sm[NS_WH1 + i] = Wh1[i];
    for (int i = tid; i < 4096; i += 128) sm[NS_WH2 + i] = Wh2[i];
    if (tid < 64) {
        sm[NS_BH1 + tid] = bh1[tid];
        sm[NS_BH2 + tid] = bh2[tid];
    }
    __syncthreads();

    const int w = tid >> 5, lane = tid & 31;
    float* sx = sm + NS_X + w * 128;
    float* sy = sm + NS_Y + w * 64;
    const float bb10 = sm[NS_BH1 + 2 * lane], bb11 = sm[NS_BH1 + 2 * lane + 1];
    const float bb20 = sm[NS_BH2 + 2 * lane], bb21 = sm[NS_BH2 + 2 * lane + 1];

    const int gw = blockIdx.x * 4 + w;
    const int nw = gridDim.x * 4;
    float* out_pos = out + (long long)N * 64;

    for (int n = gw; n < N; n += nw) {
        sx[lane]      = d_hsum[n * 64 + lane];
        sx[32 + lane] = d_hsum[n * 64 + 32 + lane];
        sx[64 + lane] = d_agg[n * 64 + lane];
        sx[96 + lane] = d_agg[n * 64 + 32 + lane];
        __syncwarp();

        // layer 1: lane computes outputs (2*lane, 2*lane+1)
        ull acc = 0ULL;
#pragma unroll 4
        for (int i = 0; i < 128; ++i) {
            const float a = sx[i];
            const ull b = reinterpret_cast<const ull*>(sm + NS_WH1 + i * 64)[lane];
            acc = fma2(pk2(a, a), b, acc);
        }
        float y0, y1;
        upk2(acc, y0, y1);
        y0 = silu_f(y0 + bb10);
        y1 = silu_f(y1 + bb11);
        *reinterpret_cast<float2*>(sy + 2 * lane) = make_float2(y0, y1);
        __syncwarp();

        // layer 2 (no silu) + skip
        acc = 0ULL;
#pragma unroll 4
        for (int i = 0; i < 64; ++i) {
            const float a = sy[i];
            const ull b = reinterpret_cast<const ull*>(sm + NS_WH2 + i * 64)[lane];
            acc = fma2(pk2(a, a), b, acc);
        }
        float r0, r1;
        upk2(acc, r0, r1);
        r0 += bb20 + sx[2 * lane];
        r1 += bb21 + sx[2 * lane + 1];
        *reinterpret_cast<float2*>(out + (long long)n * 64 + 2 * lane) = make_float2(r0, r1);

        if (lane < 2) {
            const float dg = fmaxf(d_deg[n], 1.0f);
            out_pos[n * 2 + lane] = pos[n * 2 + lane] + d_posacc[n * 2 + lane] / dg;
        }
        __syncwarp();
    }
}

// ---------------------------------------------------------------------------
extern "C" void kernel_launch(void* const* d_in, const int* in_sizes, int n_in,
                              void* d_out, int out_size)
{
    const float* h      = (const float*)d_in[0];
    const float* pos    = (const float*)d_in[1];
    const float* h_init = (const float*)d_in[2];
    const float* Wm1    = (const float*)d_in[3];
    const float* bm1    = (const float*)d_in[4];
    const float* Wm2    = (const float*)d_in[5];
    const float* bm2    = (const float*)d_in[6];
    const float* Wp1    = (const float*)d_in[7];
    const float* bp1    = (const float*)d_in[8];
    const float* Wp2    = (const float*)d_in[9];
    const float* bp2    = (const float*)d_in[10];
    const float* Wh1    = (const float*)d_in[11];
    const float* bh1    = (const float*)d_in[12];
    const float* Wh2    = (const float*)d_in[13];
    const float* bh2    = (const float*)d_in[14];
    const void*  ei     = d_in[15];

    const int N = in_sizes[0] / 64;
    const int E = in_sizes[15] / 2;
    float* out = (float*)d_out;

    cudaFuncSetAttribute(egnn_edge_kernel,
                         cudaFuncAttributeMaxDynamicSharedMemorySize, EDGE_SMEM_BYTES);
    cudaFuncSetAttribute(egnn_node_kernel,
                         cudaFuncAttributeMaxDynamicSharedMemorySize, NODE_SMEM_BYTES);

    egnn_detect_kernel<<<1, 256>>>((const long long*)ei, E);
    egnn_cvt_kernel<<<(2 * E + 255) / 256, 256>>>(ei, E);
    egnn_init_kernel<<<(N * 16 + 255) / 256, 256>>>(h, h_init, N);

    const int tiles = (E + 31) / 32;
    const int eblocks = tiles < 296 ? tiles : 296;  // 2 blocks/SM * 148 SMs
    egnn_edge_kernel<<<eblocks, 128, EDGE_SMEM_BYTES>>>(
        pos, Wm1, bm1, Wm2, bm2, Wp1, bp1, Wp2, bp2, E, N);

    egnn_node_kernel<<<592, 128, NODE_SMEM_BYTES>>>(pos, Wh1, bh1, Wh2, bh2, out, N);
}

// round 5
// speedup vs baseline: 1.7037x; 1.7037x over previous
#include <cuda_runtime.h>
#include <cuda_bf16.h>

// ---------------------------------------------------------------------------
// EGNN / SpatialNCA step.  N=50000 nodes, D=64, E=800000 edges, P=2.
//
// Inputs (metadata order):
//  0 h[N,64] 1 pos[N,2] 2 h_init[N,64]
//  3 W_msg1[129,64] 4 b_msg1[64] 5 W_msg2[64,64] 6 b_msg2[64]
//  7 W_pos1[64,64]  8 b_pos1[64] 9 W_pos2[64,1] 10 b_pos2[1]
// 11 W_h1[128,64]  12 b_h1[64]  13 W_h2[64,64]  14 b_h2[64]
// 15 edge_index[2,E]  (int32 OR int64 — detected at runtime)
// Output: [N*64 h_new][N*2 pos_new] float32.
//
// R5: edge kernel re-architected for occupancy — 512 threads/block, 1 block/SM,
// weights staged once per block, 4 independent 128-thread tile groups with
// group-local named barriers; float4 gather; float4 A-loads in GEMM;
// red.global.add.v2.f32 scatter.
// ---------------------------------------------------------------------------

typedef unsigned long long ull;

#define MAXN 50000
#define MAXD 64
#define MAXE 800000

// scratch (device globals: allocation-free rule)
__device__ __align__(16) float d_hsum[MAXN * MAXD];
__device__ __align__(16) float d_agg[MAXN * MAXD];
__device__ __align__(16) float d_posacc[MAXN * 2];
__device__ float d_deg[MAXN];
__device__ int   d_src[MAXE];
__device__ int   d_dst[MAXE];
__device__ int   d_e32flag;   // 1 if edge_index buffer is int32, 0 if int64

// ---- packed f32x2 helpers (Blackwell-only PTX) ----------------------------
__device__ __forceinline__ ull pk2(float lo, float hi) {
    ull r;
    asm("mov.b64 %0, {%1,%2};" : "=l"(r) : "f"(lo), "f"(hi));
    return r;
}
__device__ __forceinline__ void upk2(ull v, float& lo, float& hi) {
    asm("mov.b64 {%0,%1}, %2;" : "=f"(lo), "=f"(hi) : "l"(v));
}
__device__ __forceinline__ ull fma2(ull a, ull b, ull c) {
    ull d;
    asm("fma.rn.f32x2 %0, %1, %2, %3;" : "=l"(d) : "l"(a), "l"(b), "l"(c));
    return d;
}
__device__ __forceinline__ float silu_f(float x) {
    return x / (1.0f + __expf(-x));
}
__device__ __forceinline__ void red_add_v2(float* p, float x, float y) {
    asm volatile("red.global.add.v2.f32 [%0], {%1, %2};"
                 :: "l"(p), "f"(x), "f"(y) : "memory");
}

// ---- edge kernel smem layout (floats) -------------------------------------
// weights (staged once per 512-thread block)
constexpr int S_W1  = 0;                  // 129*64 = 8256
constexpr int S_W2  = S_W1 + 8256;        // 4096
constexpr int S_WP1 = S_W2 + 4096;        // 4096
constexpr int S_WP2 = S_WP1 + 4096;       // 64
constexpr int S_B1  = S_WP2 + 64;         // 64
constexpr int S_B2  = S_B1 + 64;          // 64
constexpr int S_BP1 = S_B2 + 64;          // 64
constexpr int S_BP2 = S_BP1 + 64;         // 4
constexpr int S_TILE0 = S_BP2 + 4;        // 16708 (16B aligned: 16708*4 % 16 == 0)
// per-group tile buffer (32 edges)
constexpr int T_MIN = 0;                  // 32*132 = 4224 (m_in, stride 132)
constexpr int T_T1  = T_MIN + 4224;       // 32*68  = 2176
constexpr int T_M   = T_T1 + 2176;        // 32*68  = 2176
constexpr int T_REL = T_M + 2176;         // 64
constexpr int T_WE  = T_REL + 64;         // 32
constexpr int T_IDX = T_WE + 32;          // 64 ints (src[32], dst[32])
constexpr int TILE_F = T_IDX + 64;        // 8736 floats = 34944 B (16B multiple)
constexpr int NGROUPS = 4;
constexpr int EDGE_SMEM_BYTES = (S_TILE0 + NGROUPS * TILE_F) * 4;  // 206608 B

// ---- node kernel smem layout ----------------------------------------------
constexpr int NS_WH1 = 0;                 // 128*64 = 8192
constexpr int NS_WH2 = 8192;              // 4096
constexpr int NS_BH1 = 12288;             // 64
constexpr int NS_BH2 = 12352;             // 64
constexpr int NS_X   = 12416;             // 4*128
constexpr int NS_Y   = 12928;             // 4*64
constexpr int NODE_SMEM_BYTES = (NS_Y + 256) * 4;

// ---------------------------------------------------------------------------
// Register-tiled smem GEMM: C[32][64] = act(A[32][KD] @ W[KD][64] + b)
// 128 threads (one group); thread computes 4 edges x 4 outputs, f32x2 FMAs,
// float4 A-loads (k-step 4).
// ---------------------------------------------------------------------------
template <int KD, bool DOSILU>
__device__ __forceinline__ void gemm_tile(const float* __restrict__ sA, const int ldA,
                                          const float* __restrict__ sW,
                                          const float* __restrict__ sb,
                                          float* __restrict__ sC, const int ldC,
                                          const int lt)
{
    const int tk = lt & 15;
    const int te = lt >> 4;
    const int k0 = tk << 2;   // 0..60
    const int e0 = te << 2;   // 0..28

    ull acc[4][2];
#pragma unroll
    for (int j = 0; j < 4; ++j) { acc[j][0] = 0ULL; acc[j][1] = 0ULL; }

#pragma unroll 4
    for (int i = 0; i + 3 < KD; i += 4) {
        const ulonglong2 w0 = *reinterpret_cast<const ulonglong2*>(sW + (i + 0) * 64 + k0);
        const ulonglong2 w1 = *reinterpret_cast<const ulonglong2*>(sW + (i + 1) * 64 + k0);
        const ulonglong2 w2 = *reinterpret_cast<const ulonglong2*>(sW + (i + 2) * 64 + k0);
        const ulonglong2 w3 = *reinterpret_cast<const ulonglong2*>(sW + (i + 3) * 64 + k0);
#pragma unroll
        for (int j = 0; j < 4; ++j) {
            const float4 a = *reinterpret_cast<const float4*>(sA + (e0 + j) * ldA + i);
            ull ap;
            ap = pk2(a.x, a.x);
            acc[j][0] = fma2(ap, w0.x, acc[j][0]);
            acc[j][1] = fma2(ap, w0.y, acc[j][1]);
            ap = pk2(a.y, a.y);
            acc[j][0] = fma2(ap, w1.x, acc[j][0]);
            acc[j][1] = fma2(ap, w1.y, acc[j][1]);
            ap = pk2(a.z, a.z);
            acc[j][0] = fma2(ap, w2.x, acc[j][0]);
            acc[j][1] = fma2(ap, w2.y, acc[j][1]);
            ap = pk2(a.w, a.w);
            acc[j][0] = fma2(ap, w3.x, acc[j][0]);
            acc[j][1] = fma2(ap, w3.y, acc[j][1]);
        }
    }
    if (KD & 3) {   // remainder (KD=129 -> 1 extra k-step)
#pragma unroll
        for (int i = KD & ~3; i < KD; ++i) {
            const ulonglong2 w0 = *reinterpret_cast<const ulonglong2*>(sW + i * 64 + k0);
#pragma unroll
            for (int j = 0; j < 4; ++j) {
                const float a = sA[(e0 + j) * ldA + i];
                const ull ap = pk2(a, a);
                acc[j][0] = fma2(ap, w0.x, acc[j][0]);
                acc[j][1] = fma2(ap, w0.y, acc[j][1]);
            }
        }
    }

    const float bb0 = sb[k0], bb1 = sb[k0 + 1], bb2 = sb[k0 + 2], bb3 = sb[k0 + 3];
#pragma unroll
    for (int j = 0; j < 4; ++j) {
        float r0, r1, r2, r3;
        upk2(acc[j][0], r0, r1);
        upk2(acc[j][1], r2, r3);
        r0 += bb0; r1 += bb1; r2 += bb2; r3 += bb3;
        if (DOSILU) {
            r0 = silu_f(r0); r1 = silu_f(r1);
            r2 = silu_f(r2); r3 = silu_f(r3);
        }
        *reinterpret_cast<float4*>(sC + (e0 + j) * ldC + k0) = make_float4(r0, r1, r2, r3);
    }
}

// ---------------------------------------------------------------------------
// Kernel 0a: detect edge_index dtype (int32 vs int64).
// ---------------------------------------------------------------------------
__global__ void egnn_detect_kernel(const long long* __restrict__ ei, const int E)
{
    __shared__ int bad;
    if (threadIdx.x == 0) bad = 0;
    __syncthreads();
    const int cnt = E < 1024 ? E : 1024;
    for (int i = threadIdx.x; i < cnt; i += blockDim.x) {
        const long long v = ei[i];
        if (v < 0 || v > 0x7FFFFFFFLL) bad = 1;
    }
    __syncthreads();
    if (threadIdx.x == 0) d_e32flag = bad;   // bad -> data is int32
}

// Kernel 0b: normalize indices into int scratch arrays.
__global__ void egnn_cvt_kernel(const void* __restrict__ ei, const int E)
{
    const int i = blockIdx.x * blockDim.x + threadIdx.x;
    if (i >= 2 * E) return;
    int v;
    if (d_e32flag) v = ((const int*)ei)[i];
    else           v = (int)(((const long long*)ei)[i]);
    if (i < E) d_src[i] = v;
    else       d_dst[i - E] = v;
}

// ---------------------------------------------------------------------------
// Kernel 1: hsum = h + h_init; zero accumulators.
// ---------------------------------------------------------------------------
__global__ void egnn_init_kernel(const float* __restrict__ h,
                                 const float* __restrict__ hi, const int N)
{
    const int i = blockIdx.x * blockDim.x + threadIdx.x;
    const int n4 = N * 16;  // float4 count for N*64
    if (i < n4) {
        const float4 a = reinterpret_cast<const float4*>(h)[i];
        const float4 b = reinterpret_cast<const float4*>(hi)[i];
        float4 s;
        s.x = a.x + b.x; s.y = a.y + b.y; s.z = a.z + b.z; s.w = a.w + b.w;
        reinterpret_cast<float4*>(d_hsum)[i] = s;
        reinterpret_cast<float4*>(d_agg)[i] = make_float4(0.f, 0.f, 0.f, 0.f);
    }
    if (i < N) d_deg[i] = 0.0f;
    if (i < N * 2) d_posacc[i] = 0.0f;
}

// ---------------------------------------------------------------------------
// Kernel 2: persistent edge kernel. 512 threads = 4 independent 128-thread
// groups; each group streams 32-edge tiles with its own smem buffers.
// ---------------------------------------------------------------------------
__global__ void __launch_bounds__(512, 1)
egnn_edge_kernel(const float* __restrict__ pos,
                 const float* __restrict__ Wm1, const float* __restrict__ bm1,
                 const float* __restrict__ Wm2, const float* __restrict__ bm2,
                 const float* __restrict__ Wp1, const float* __restrict__ bp1,
                 const float* __restrict__ Wp2, const float* __restrict__ bp2,
                 const int E, const int N)
{
    extern __shared__ float sm[];
    const int tid = threadIdx.x;

    // stage all weights once per block (512 threads)
    for (int i = tid; i < 8256; i += 512) sm[S_W1 + i] = Wm1[i];
    for (int i = tid; i < 4096; i += 512) sm[S_W2 + i] = Wm2[i];
    for (int i = tid; i < 4096; i += 512) sm[S_WP1 + i] = Wp1[i];
    if (tid < 64) {
        sm[S_WP2 + tid] = Wp2[tid];
        sm[S_B1 + tid] = bm1[tid];
        sm[S_B2 + tid] = bm2[tid];
        sm[S_BP1 + tid] = bp1[tid];
    }
    if (tid == 0) sm[S_BP2] = bp2[0];
    __syncthreads();

    const int g  = tid >> 7;     // group 0..3
    const int lt = tid & 127;    // lane within group
    float* tb = sm + S_TILE0 + g * TILE_F;
    int* sidx = reinterpret_cast<int*>(tb + T_IDX);  // [0..31]=src, [32..63]=dst

    // group-local barrier (named barriers 1..4, 128 threads each)
    const int barid = g + 1;
#define GBAR() asm volatile("bar.sync %0, 128;" :: "r"(barid) : "memory")

    const int nTiles = (E + 31) >> 5;
    const int stride = gridDim.x * NGROUPS;

    for (int t = blockIdx.x * NGROUPS + g; t < nTiles; t += stride) {
        const int eBase = t << 5;

        if (lt < 32) {
            const int e = eBase + lt;
            int s = -1, d = -1;
            if (e < E) { s = d_src[e]; d = d_dst[e]; }
            if ((unsigned)s >= (unsigned)N) s = -1;   // safety clamp
            if ((unsigned)d >= (unsigned)N) d = -1;
            sidx[lt] = s;
            sidx[32 + lt] = d;
        }
        GBAR();

        // gather m_in = [h[dst](64), h[src](64), d2] with float4 loads
        for (int idx = lt; idx < 32 * 32; idx += 128) {
            const int e = idx >> 5, q = idx & 31;        // q: 32 float4 per edge
            const int node = (q < 16) ? sidx[32 + e] : sidx[e];
            float4 v = make_float4(0.f, 0.f, 0.f, 0.f);
            if (node >= 0)
                v = reinterpret_cast<const float4*>(d_hsum)[node * 16 + (q & 15)];
            *reinterpret_cast<float4*>(tb + T_MIN + e * 132 + q * 4) = v;
        }
        if (lt < 32) {
            const int s = sidx[lt], d = sidx[32 + lt];
            float r0 = 0.0f, r1 = 0.0f;
            if (s >= 0 && d >= 0) {
                r0 = pos[d * 2 + 0] - pos[s * 2 + 0];
                r1 = pos[d * 2 + 1] - pos[s * 2 + 1];
            }
            tb[T_REL + lt * 2 + 0] = r0;
            tb[T_REL + lt * 2 + 1] = r1;
            tb[T_MIN + lt * 132 + 128] = r0 * r0 + r1 * r1;
        }
        GBAR();

        // phi_e layer 1: t1 = silu(m_in @ W_msg1 + b_msg1)
        gemm_tile<129, true>(tb + T_MIN, 132, sm + S_W1, sm + S_B1, tb + T_T1, 68, lt);
        GBAR();
        // phi_e layer 2: m = silu(t1 @ W_msg2 + b_msg2)
        gemm_tile<64, true>(tb + T_T1, 68, sm + S_W2, sm + S_B2, tb + T_M, 68, lt);
        GBAR();
        // phi_x layer 1: t2 = silu(m @ W_pos1 + b_pos1)   (reuses T1 slot)
        gemm_tile<64, true>(tb + T_M, 68, sm + S_WP1, sm + S_BP1, tb + T_T1, 68, lt);
        GBAR();
        // phi_x layer 2: w = t2 @ W_pos2 + b_pos2 (scalar per edge)
        if (lt < 32) {
            float acc = sm[S_BP2];
            const float* row = tb + T_T1 + lt * 68;
#pragma unroll 8
            for (int i = 0; i < 64; ++i) acc += row[i] * sm[S_WP2 + i];
            tb[T_WE + lt] = acc;
        }
        GBAR();

        // scatter: agg += m (v2 red), posacc += rel*w (v2 red), deg += 1
        for (int idx = lt; idx < 32 * 32; idx += 128) {
            const int e = idx >> 5, k2 = idx & 31;
            const int d = sidx[32 + e];
            if (d >= 0) {
                const float2 v = *reinterpret_cast<const float2*>(tb + T_M + e * 68 + k2 * 2);
                red_add_v2(&d_agg[d * 64 + k2 * 2], v.x, v.y);
            }
        }
        if (lt < 32) {
            const int d = sidx[32 + lt];
            if (d >= 0) {
                const float wv = tb[T_WE + lt];
                red_add_v2(&d_posacc[d * 2],
                           tb[T_REL + lt * 2 + 0] * wv,
                           tb[T_REL + lt * 2 + 1] * wv);
                atomicAdd(&d_deg[d], 1.0f);
            }
        }
        GBAR();   // protect sidx/T_M/T_REL before next tile overwrites
    }
#undef GBAR
}

// ---------------------------------------------------------------------------
// Kernel 3: node update (phi_h) + skip connections + pos update. Warp/node.
// ---------------------------------------------------------------------------
__global__ void __launch_bounds__(128, 4)
egnn_node_kernel(const float* __restrict__ pos,
                 const float* __restrict__ Wh1, const float* __restrict__ bh1,
                 const float* __restrict__ Wh2, const float* __restrict__ bh2,
                 float* __restrict__ out, const int N)
{
    extern __shared__ float sm[];
    const int tid = threadIdx.x;

    for (int i = tid; i < 8192; i += 128) sm[NS_WH1 + i] = Wh1[i];
    for (int i = tid; i < 4096; i += 128) sm[NS_WH2 + i] = Wh2[i];
    if (tid < 64) {
        sm[NS_BH1 + tid] = bh1[tid];
        sm[NS_BH2 + tid] = bh2[tid];
    }
    __syncthreads();

    const int w = tid >> 5, lane = tid & 31;
    float* sx = sm + NS_X + w * 128;
    float* sy = sm + NS_Y + w * 64;
    const float bb10 = sm[NS_BH1 + 2 * lane], bb11 = sm[NS_BH1 + 2 * lane + 1];
    const float bb20 = sm[NS_BH2 + 2 * lane], bb21 = sm[NS_BH2 + 2 * lane + 1];

    const int gw = blockIdx.x * 4 + w;
    const int nw = gridDim.x * 4;
    float* out_pos = out + (long long)N * 64;

    for (int n = gw; n < N; n += nw) {
        sx[lane]      = d_hsum[n * 64 + lane];
        sx[32 + lane] = d_hsum[n * 64 + 32 + lane];
        sx[64 + lane] = d_agg[n * 64 + lane];
        sx[96 + lane] = d_agg[n * 64 + 32 + lane];
        __syncwarp();

        // layer 1: lane computes outputs (2*lane, 2*lane+1)
        ull acc = 0ULL;
#pragma unroll 4
        for (int i = 0; i < 128; ++i) {
            const float a = sx[i];
            const ull b = reinterpret_cast<const ull*>(sm + NS_WH1 + i * 64)[lane];
            acc = fma2(pk2(a, a), b, acc);
        }
        float y0, y1;
        upk2(acc, y0, y1);
        y0 = silu_f(y0 + bb10);
        y1 = silu_f(y1 + bb11);
        *reinterpret_cast<float2*>(sy + 2 * lane) = make_float2(y0, y1);
        __syncwarp();

        // layer 2 (no silu) + skip
        acc = 0ULL;
#pragma unroll 4
        for (int i = 0; i < 64; ++i) {
            const float a = sy[i];
            const ull b = reinterpret_cast<const ull*>(sm + NS_WH2 + i * 64)[lane];
            acc = fma2(pk2(a, a), b, acc);
        }
        float r0, r1;
        upk2(acc, r0, r1);
        r0 += bb20 + sx[2 * lane];
        r1 += bb21 + sx[2 * lane + 1];
        *reinterpret_cast<float2*>(out + (long long)n * 64 + 2 * lane) = make_float2(r0, r1);

        if (lane < 2) {
            const float dg = fmaxf(d_deg[n], 1.0f);
            out_pos[n * 2 + lane] = pos[n * 2 + lane] + d_posacc[n * 2 + lane] / dg;
        }
        __syncwarp();
    }
}

// ---------------------------------------------------------------------------
extern "C" void kernel_launch(void* const* d_in, const int* in_sizes, int n_in,
                              void* d_out, int out_size)
{
    const float* h      = (const float*)d_in[0];
    const float* pos    = (const float*)d_in[1];
    const float* h_init = (const float*)d_in[2];
    const float* Wm1    = (const float*)d_in[3];
    const float* bm1    = (const float*)d_in[4];
    const float* Wm2    = (const float*)d_in[5];
    const float* bm2    = (const float*)d_in[6];
    const float* Wp1    = (const float*)d_in[7];
    const float* bp1    = (const float*)d_in[8];
    const float* Wp2    = (const float*)d_in[9];
    const float* bp2    = (const float*)d_in[10];
    const float* Wh1    = (const float*)d_in[11];
    const float* bh1    = (const float*)d_in[12];
    const float* Wh2    = (const float*)d_in[13];
    const float* bh2    = (const float*)d_in[14];
    const void*  ei     = d_in[15];

    const int N = in_sizes[0] / 64;
    const int E = in_sizes[15] / 2;
    float* out = (float*)d_out;

    cudaFuncSetAttribute(egnn_edge_kernel,
                         cudaFuncAttributeMaxDynamicSharedMemorySize, EDGE_SMEM_BYTES);
    cudaFuncSetAttribute(egnn_node_kernel,
                         cudaFuncAttributeMaxDynamicSharedMemorySize, NODE_SMEM_BYTES);

    egnn_detect_kernel<<<1, 256>>>((const long long*)ei, E);
    egnn_cvt_kernel<<<(2 * E + 255) / 256, 256>>>(ei, E);
    egnn_init_kernel<<<(N * 16 + 255) / 256, 256>>>(h, h_init, N);

    const int tiles = (E + 31) / 32;
    int eblocks = (tiles + NGROUPS - 1) / NGROUPS;
    if (eblocks > 148) eblocks = 148;   // 1 block/SM, persistent
    egnn_edge_kernel<<<eblocks, 512, EDGE_SMEM_BYTES>>>(
        pos, Wm1, bm1, Wm2, bm2, Wp1, bp1, Wp2, bp2, E, N);

    egnn_node_kernel<<<592, 128, NODE_SMEM_BYTES>>>(pos, Wh1, bh1, Wh2, bh2, out, N);
}

// round 6
// speedup vs baseline: 1.8212x; 1.0689x over previous
#include <cuda_runtime.h>
#include <cuda_bf16.h>

// ---------------------------------------------------------------------------
// EGNN / SpatialNCA step.  N=50000 nodes, D=64, E=800000 edges, P=2.
//
// R6: edge kernel — warp remap for 1-wavefront W loads (k0 = outhalf*32+tk*4,
// edges strided), in-place smem reuse (t1/t2 overwrite m_in) to fit 5 groups
// of 128 threads (640 thr/block, 20 warps/SM).
// ---------------------------------------------------------------------------

typedef unsigned long long ull;

#define MAXN 50000
#define MAXD 64
#define MAXE 800000

// scratch (device globals: allocation-free rule)
__device__ __align__(16) float d_hsum[MAXN * MAXD];
__device__ __align__(16) float d_agg[MAXN * MAXD];
__device__ __align__(16) float d_posacc[MAXN * 2];
__device__ float d_deg[MAXN];
__device__ int   d_src[MAXE];
__device__ int   d_dst[MAXE];
__device__ int   d_e32flag;   // 1 if edge_index buffer is int32, 0 if int64

// ---- packed f32x2 helpers ---------------------------------------------------
__device__ __forceinline__ ull pk2(float lo, float hi) {
    ull r;
    asm("mov.b64 %0, {%1,%2};" : "=l"(r) : "f"(lo), "f"(hi));
    return r;
}
__device__ __forceinline__ void upk2(ull v, float& lo, float& hi) {
    asm("mov.b64 {%0,%1}, %2;" : "=f"(lo), "=f"(hi) : "l"(v));
}
__device__ __forceinline__ ull fma2(ull a, ull b, ull c) {
    ull d;
    asm("fma.rn.f32x2 %0, %1, %2, %3;" : "=l"(d) : "l"(a), "l"(b), "l"(c));
    return d;
}
__device__ __forceinline__ float silu_f(float x) {
    return x / (1.0f + __expf(-x));
}
__device__ __forceinline__ void red_add_v2(float* p, float x, float y) {
    asm volatile("red.global.add.v2.f32 [%0], {%1, %2};"
                 :: "l"(p), "f"(x), "f"(y) : "memory");
}

// ---- edge kernel smem layout (floats) -------------------------------------
// weights (staged once per block)
constexpr int S_W1  = 0;                  // 129*64 = 8256
constexpr int S_W2  = S_W1 + 8256;        // 4096
constexpr int S_WP1 = S_W2 + 4096;        // 4096
constexpr int S_WP2 = S_WP1 + 4096;       // 64
constexpr int S_B1  = S_WP2 + 64;         // 64
constexpr int S_B2  = S_B1 + 64;          // 64
constexpr int S_BP1 = S_B2 + 64;          // 64
constexpr int S_BP2 = S_BP1 + 64;         // 4
constexpr int S_TILE0 = S_BP2 + 4;        // 16708 floats (66832 B, 16B aligned)
// per-group tile buffer (32 edges), in-place reuse:
//   T_MIN holds m_in (stride 132) for GEMM1, then t1 (GEMM1 out, GEMM2 in),
//   then t2 (GEMM3 out, phi_x in). T_M holds m (GEMM2 out, GEMM3 in, scatter).
constexpr int T_MIN = 0;                  // 32*132 = 4224
constexpr int T_M   = T_MIN + 4224;       // 32*68  = 2176
constexpr int T_REL = T_M + 2176;         // 64
constexpr int T_WE  = T_REL + 64;         // 32
constexpr int T_IDX = T_WE + 32;          // 64 ints (src[32], dst[32])
constexpr int TILE_F = T_IDX + 64;        // 6560 floats = 26240 B (16B mult)
constexpr int NGROUPS = 5;
constexpr int NTHREADS = NGROUPS * 128;   // 640
constexpr int EDGE_SMEM_BYTES = (S_TILE0 + NGROUPS * TILE_F) * 4;  // 198032 B

// ---- node kernel smem layout ----------------------------------------------
constexpr int NS_WH1 = 0;                 // 128*64 = 8192
constexpr int NS_WH2 = 8192;              // 4096
constexpr int NS_BH1 = 12288;             // 64
constexpr int NS_BH2 = 12352;             // 64
constexpr int NS_X   = 12416;             // 4*128
constexpr int NS_Y   = 12928;             // 4*64
constexpr int NODE_SMEM_BYTES = (NS_Y + 256) * 4;

// ---------------------------------------------------------------------------
// Register-tiled smem GEMM: C[32][64] = act(A[32][KD] @ W[KD][64] + b)
// 128 threads (one group). Warp mapping chosen so each W LDS.128 covers
// exactly one 128B-aligned block (1 wavefront) and A loads are conflict-free:
//   w  = lt>>5 (warp), tk = lt&7, te = (lt>>3)&3
//   k0 = (w&1)*32 + tk*4   (output col base)
//   edges handled: e = (w>>1)*16 + te + j*4, j = 0..3
// If SPLIT, a group barrier separates compute from store (for in-place C=A).
// ---------------------------------------------------------------------------
template <int KD, bool DOSILU, bool SPLIT>
__device__ __forceinline__ void gemm_tile(const float* __restrict__ sA, const int ldA,
                                          const float* __restrict__ sW,
                                          const float* __restrict__ sb,
                                          float* __restrict__ sC, const int ldC,
                                          const int lt, const int barid)
{
    const int w  = lt >> 5;
    const int tk = lt & 7;
    const int te = (lt >> 3) & 3;
    const int k0 = (w & 1) * 32 + tk * 4;     // 0..60
    const int eb = (w >> 1) * 16 + te;        // edge base; rows eb + j*4

    ull acc[4][2];
#pragma unroll
    for (int j = 0; j < 4; ++j) { acc[j][0] = 0ULL; acc[j][1] = 0ULL; }

#pragma unroll 4
    for (int i = 0; i + 3 < KD; i += 4) {
        const ulonglong2 w0 = *reinterpret_cast<const ulonglong2*>(sW + (i + 0) * 64 + k0);
        const ulonglong2 w1 = *reinterpret_cast<const ulonglong2*>(sW + (i + 1) * 64 + k0);
        const ulonglong2 w2 = *reinterpret_cast<const ulonglong2*>(sW + (i + 2) * 64 + k0);
        const ulonglong2 w3 = *reinterpret_cast<const ulonglong2*>(sW + (i + 3) * 64 + k0);
#pragma unroll
        for (int j = 0; j < 4; ++j) {
            const float4 a = *reinterpret_cast<const float4*>(sA + (eb + j * 4) * ldA + i);
            ull ap;
            ap = pk2(a.x, a.x);
            acc[j][0] = fma2(ap, w0.x, acc[j][0]);
            acc[j][1] = fma2(ap, w0.y, acc[j][1]);
            ap = pk2(a.y, a.y);
            acc[j][0] = fma2(ap, w1.x, acc[j][0]);
            acc[j][1] = fma2(ap, w1.y, acc[j][1]);
            ap = pk2(a.z, a.z);
            acc[j][0] = fma2(ap, w2.x, acc[j][0]);
            acc[j][1] = fma2(ap, w2.y, acc[j][1]);
            ap = pk2(a.w, a.w);
            acc[j][0] = fma2(ap, w3.x, acc[j][0]);
            acc[j][1] = fma2(ap, w3.y, acc[j][1]);
        }
    }
    if (KD & 3) {   // remainder (KD=129 -> 1 extra k-step)
#pragma unroll
        for (int i = KD & ~3; i < KD; ++i) {
            const ulonglong2 w0 = *reinterpret_cast<const ulonglong2*>(sW + i * 64 + k0);
#pragma unroll
            for (int j = 0; j < 4; ++j) {
                const float a = sA[(eb + j * 4) * ldA + i];
                const ull ap = pk2(a, a);
                acc[j][0] = fma2(ap, w0.x, acc[j][0]);
                acc[j][1] = fma2(ap, w0.y, acc[j][1]);
            }
        }
    }

    if (SPLIT)   // all reads of sA done before sC (== sA region) is written
        asm volatile("bar.sync %0, 128;" :: "r"(barid) : "memory");

    const float bb0 = sb[k0], bb1 = sb[k0 + 1], bb2 = sb[k0 + 2], bb3 = sb[k0 + 3];
#pragma unroll
    for (int j = 0; j < 4; ++j) {
        float r0, r1, r2, r3;
        upk2(acc[j][0], r0, r1);
        upk2(acc[j][1], r2, r3);
        r0 += bb0; r1 += bb1; r2 += bb2; r3 += bb3;
        if (DOSILU) {
            r0 = silu_f(r0); r1 = silu_f(r1);
            r2 = silu_f(r2); r3 = silu_f(r3);
        }
        *reinterpret_cast<float4*>(sC + (eb + j * 4) * ldC + k0) = make_float4(r0, r1, r2, r3);
    }
}

// ---------------------------------------------------------------------------
// Kernel 0a: detect edge_index dtype (int32 vs int64).
// ---------------------------------------------------------------------------
__global__ void egnn_detect_kernel(const long long* __restrict__ ei, const int E)
{
    __shared__ int bad;
    if (threadIdx.x == 0) bad = 0;
    __syncthreads();
    const int cnt = E < 1024 ? E : 1024;
    for (int i = threadIdx.x; i < cnt; i += blockDim.x) {
        const long long v = ei[i];
        if (v < 0 || v > 0x7FFFFFFFLL) bad = 1;
    }
    __syncthreads();
    if (threadIdx.x == 0) d_e32flag = bad;   // bad -> data is int32
}

// Kernel 0b: normalize indices into int scratch arrays.
__global__ void egnn_cvt_kernel(const void* __restrict__ ei, const int E)
{
    const int i = blockIdx.x * blockDim.x + threadIdx.x;
    if (i >= 2 * E) return;
    int v;
    if (d_e32flag) v = ((const int*)ei)[i];
    else           v = (int)(((const long long*)ei)[i]);
    if (i < E) d_src[i] = v;
    else       d_dst[i - E] = v;
}

// ---------------------------------------------------------------------------
// Kernel 1: hsum = h + h_init; zero accumulators.
// ---------------------------------------------------------------------------
__global__ void egnn_init_kernel(const float* __restrict__ h,
                                 const float* __restrict__ hi, const int N)
{
    const int i = blockIdx.x * blockDim.x + threadIdx.x;
    const int n4 = N * 16;  // float4 count for N*64
    if (i < n4) {
        const float4 a = reinterpret_cast<const float4*>(h)[i];
        const float4 b = reinterpret_cast<const float4*>(hi)[i];
        float4 s;
        s.x = a.x + b.x; s.y = a.y + b.y; s.z = a.z + b.z; s.w = a.w + b.w;
        reinterpret_cast<float4*>(d_hsum)[i] = s;
        reinterpret_cast<float4*>(d_agg)[i] = make_float4(0.f, 0.f, 0.f, 0.f);
    }
    if (i < N) d_deg[i] = 0.0f;
    if (i < N * 2) d_posacc[i] = 0.0f;
}

// ---------------------------------------------------------------------------
// Kernel 2: persistent edge kernel. 640 threads = 5 independent 128-thread
// groups; each group streams 32-edge tiles with its own smem buffers.
// ---------------------------------------------------------------------------
__global__ void __launch_bounds__(NTHREADS, 1)
egnn_edge_kernel(const float* __restrict__ pos,
                 const float* __restrict__ Wm1, const float* __restrict__ bm1,
                 const float* __restrict__ Wm2, const float* __restrict__ bm2,
                 const float* __restrict__ Wp1, const float* __restrict__ bp1,
                 const float* __restrict__ Wp2, const float* __restrict__ bp2,
                 const int E, const int N)
{
    extern __shared__ float sm[];
    const int tid = threadIdx.x;

    // stage all weights once per block
    for (int i = tid; i < 8256; i += NTHREADS) sm[S_W1 + i] = Wm1[i];
    for (int i = tid; i < 4096; i += NTHREADS) sm[S_W2 + i] = Wm2[i];
    for (int i = tid; i < 4096; i += NTHREADS) sm[S_WP1 + i] = Wp1[i];
    if (tid < 64) {
        sm[S_WP2 + tid] = Wp2[tid];
        sm[S_B1 + tid] = bm1[tid];
        sm[S_B2 + tid] = bm2[tid];
        sm[S_BP1 + tid] = bp1[tid];
    }
    if (tid == 0) sm[S_BP2] = bp2[0];
    __syncthreads();

    const int g  = tid >> 7;     // group 0..4
    const int lt = tid & 127;    // lane within group
    float* tb = sm + S_TILE0 + g * TILE_F;
    int* sidx = reinterpret_cast<int*>(tb + T_IDX);  // [0..31]=src, [32..63]=dst

    const int barid = g + 1;     // named barriers 1..5, 128 threads each
#define GBAR() asm volatile("bar.sync %0, 128;" :: "r"(barid) : "memory")

    const int nTiles = (E + 31) >> 5;
    const int stride = gridDim.x * NGROUPS;

    for (int t = blockIdx.x * NGROUPS + g; t < nTiles; t += stride) {
        const int eBase = t << 5;

        if (lt < 32) {
            const int e = eBase + lt;
            int s = -1, d = -1;
            if (e < E) { s = d_src[e]; d = d_dst[e]; }
            if ((unsigned)s >= (unsigned)N) s = -1;   // safety clamp
            if ((unsigned)d >= (unsigned)N) d = -1;
            sidx[lt] = s;
            sidx[32 + lt] = d;
        }
        GBAR();

        // gather m_in = [h[dst](64), h[src](64), d2] with float4 loads
        for (int idx = lt; idx < 32 * 32; idx += 128) {
            const int e = idx >> 5, q = idx & 31;        // 32 float4 per edge
            const int node = (q < 16) ? sidx[32 + e] : sidx[e];
            float4 v = make_float4(0.f, 0.f, 0.f, 0.f);
            if (node >= 0)
                v = reinterpret_cast<const float4*>(d_hsum)[node * 16 + (q & 15)];
            *reinterpret_cast<float4*>(tb + T_MIN + e * 132 + q * 4) = v;
        }
        if (lt < 32) {
            const int s = sidx[lt], d = sidx[32 + lt];
            float r0 = 0.0f, r1 = 0.0f;
            if (s >= 0 && d >= 0) {
                r0 = pos[d * 2 + 0] - pos[s * 2 + 0];
                r1 = pos[d * 2 + 1] - pos[s * 2 + 1];
            }
            tb[T_REL + lt * 2 + 0] = r0;
            tb[T_REL + lt * 2 + 1] = r1;
            tb[T_MIN + lt * 132 + 128] = r0 * r0 + r1 * r1;
        }
        GBAR();

        // phi_e layer 1: t1 = silu(m_in @ W_msg1 + b_msg1); t1 overwrites m_in
        // (SPLIT: internal barrier between A-reads and C-stores)
        gemm_tile<129, true, true>(tb + T_MIN, 132, sm + S_W1, sm + S_B1,
                                   tb + T_MIN, 132, lt, barid);
        GBAR();
        // phi_e layer 2: m = silu(t1 @ W_msg2 + b_msg2) -> T_M
        gemm_tile<64, true, false>(tb + T_MIN, 132, sm + S_W2, sm + S_B2,
                                   tb + T_M, 68, lt, barid);
        GBAR();
        // phi_x layer 1: t2 = silu(m @ W_pos1 + b_pos1) -> T_MIN (t1 is dead)
        gemm_tile<64, true, false>(tb + T_M, 68, sm + S_WP1, sm + S_BP1,
                                   tb + T_MIN, 132, lt, barid);
        GBAR();
        // phi_x layer 2: w = t2 @ W_pos2 + b_pos2 (scalar per edge)
        if (lt < 32) {
            float acc = sm[S_BP2];
            const float* row = tb + T_MIN + lt * 132;
#pragma unroll 8
            for (int i = 0; i < 64; ++i) acc += row[i] * sm[S_WP2 + i];
            tb[T_WE + lt] = acc;
        }
        GBAR();

        // scatter: agg += m (v2 red), posacc += rel*w (v2 red), deg += 1
        for (int idx = lt; idx < 32 * 32; idx += 128) {
            const int e = idx >> 5, k2 = idx & 31;
            const int d = sidx[32 + e];
            if (d >= 0) {
                const float2 v = *reinterpret_cast<const float2*>(tb + T_M + e * 68 + k2 * 2);
                red_add_v2(&d_agg[d * 64 + k2 * 2], v.x, v.y);
            }
        }
        if (lt < 32) {
            const int d = sidx[32 + lt];
            if (d >= 0) {
                const float wv = tb[T_WE + lt];
                red_add_v2(&d_posacc[d * 2],
                           tb[T_REL + lt * 2 + 0] * wv,
                           tb[T_REL + lt * 2 + 1] * wv);
                atomicAdd(&d_deg[d], 1.0f);
            }
        }
        GBAR();   // protect sidx/T_M/T_REL before next tile overwrites
    }
#undef GBAR
}

// ---------------------------------------------------------------------------
// Kernel 3: node update (phi_h) + skip connections + pos update. Warp/node.
// ---------------------------------------------------------------------------
__global__ void __launch_bounds__(128, 4)
egnn_node_kernel(const float* __restrict__ pos,
                 const float* __restrict__ Wh1, const float* __restrict__ bh1,
                 const float* __restrict__ Wh2, const float* __restrict__ bh2,
                 float* __restrict__ out, const int N)
{
    extern __shared__ float sm[];
    const int tid = threadIdx.x;

    for (int i = tid; i < 8192; i += 128) sm[NS_WH1 + i] = Wh1[i];
    for (int i = tid; i < 4096; i += 128) sm[NS_WH2 + i] = Wh2[i];
    if (tid < 64) {
        sm[NS_BH1 + tid] = bh1[tid];
        sm[NS_BH2 + tid] = bh2[tid];
    }
    __syncthreads();

    const int w = tid >> 5, lane = tid & 31;
    float* sx = sm + NS_X + w * 128;
    float* sy = sm + NS_Y + w * 64;
    const float bb10 = sm[NS_BH1 + 2 * lane], bb11 = sm[NS_BH1 + 2 * lane + 1];
    const float bb20 = sm[NS_BH2 + 2 * lane], bb21 = sm[NS_BH2 + 2 * lane + 1];

    const int gw = blockIdx.x * 4 + w;
    const int nw = gridDim.x * 4;
    float* out_pos = out + (long long)N * 64;

    for (int n = gw; n < N; n += nw) {
        sx[lane]      = d_hsum[n * 64 + lane];
        sx[32 + lane] = d_hsum[n * 64 + 32 + lane];
        sx[64 + lane] = d_agg[n * 64 + lane];
        sx[96 + lane] = d_agg[n * 64 + 32 + lane];
        __syncwarp();

        // layer 1: lane computes outputs (2*lane, 2*lane+1)
        ull acc = 0ULL;
#pragma unroll 4
        for (int i = 0; i < 128; ++i) {
            const float a = sx[i];
            const ull b = reinterpret_cast<const ull*>(sm + NS_WH1 + i * 64)[lane];
            acc = fma2(pk2(a, a), b, acc);
        }
        float y0, y1;
        upk2(acc, y0, y1);
        y0 = silu_f(y0 + bb10);
        y1 = silu_f(y1 + bb11);
        *reinterpret_cast<float2*>(sy + 2 * lane) = make_float2(y0, y1);
        __syncwarp();

        // layer 2 (no silu) + skip
        acc = 0ULL;
#pragma unroll 4
        for (int i = 0; i < 64; ++i) {
            const float a = sy[i];
            const ull b = reinterpret_cast<const ull*>(sm + NS_WH2 + i * 64)[lane];
            acc = fma2(pk2(a, a), b, acc);
        }
        float r0, r1;
        upk2(acc, r0, r1);
        r0 += bb20 + sx[2 * lane];
        r1 += bb21 + sx[2 * lane + 1];
        *reinterpret_cast<float2*>(out + (long long)n * 64 + 2 * lane) = make_float2(r0, r1);

        if (lane < 2) {
            const float dg = fmaxf(d_deg[n], 1.0f);
            out_pos[n * 2 + lane] = pos[n * 2 + lane] + d_posacc[n * 2 + lane] / dg;
        }
        __syncwarp();
    }
}

// ---------------------------------------------------------------------------
extern "C" void kernel_launch(void* const* d_in, const int* in_sizes, int n_in,
                              void* d_out, int out_size)
{
    const float* h      = (const float*)d_in[0];
    const float* pos    = (const float*)d_in[1];
    const float* h_init = (const float*)d_in[2];
    const float* Wm1    = (const float*)d_in[3];
    const float* bm1    = (const float*)d_in[4];
    const float* Wm2    = (const float*)d_in[5];
    const float* bm2    = (const float*)d_in[6];
    const float* Wp1    = (const float*)d_in[7];
    const float* bp1    = (const float*)d_in[8];
    const float* Wp2    = (const float*)d_in[9];
    const float* bp2    = (const float*)d_in[10];
    const float* Wh1    = (const float*)d_in[11];
    const float* bh1    = (const float*)d_in[12];
    const float* Wh2    = (const float*)d_in[13];
    const float* bh2    = (const float*)d_in[14];
    const void*  ei     = d_in[15];

    const int N = in_sizes[0] / 64;
    const int E = in_sizes[15] / 2;
    float* out = (float*)d_out;

    cudaFuncSetAttribute(egnn_edge_kernel,
                         cudaFuncAttributeMaxDynamicSharedMemorySize, EDGE_SMEM_BYTES);
    cudaFuncSetAttribute(egnn_node_kernel,
                         cudaFuncAttributeMaxDynamicSharedMemorySize, NODE_SMEM_BYTES);

    egnn_detect_kernel<<<1, 256>>>((const long long*)ei, E);
    egnn_cvt_kernel<<<(2 * E + 255) / 256, 256>>>(ei, E);
    egnn_init_kernel<<<(N * 16 + 255) / 256, 256>>>(h, h_init, N);

    const int tiles = (E + 31) / 32;
    int eblocks = (tiles + NGROUPS - 1) / NGROUPS;
    if (eblocks > 148) eblocks = 148;   // 1 block/SM, persistent
    egnn_edge_kernel<<<eblocks, NTHREADS, EDGE_SMEM_BYTES>>>(
        pos, Wm1, bm1, Wm2, bm2, Wp1, bp1, Wp2, bp2, E, N);

    egnn_node_kernel<<<592, 128, NODE_SMEM_BYTES>>>(pos, Wh1, bh1, Wh2, bh2, out, N);
}

// round 9
// speedup vs baseline: 2.1505x; 1.1809x over previous
#include <cuda_runtime.h>
#include <cuda_bf16.h>
#include <stdint.h>

// ---------------------------------------------------------------------------
// EGNN / SpatialNCA step.  N=50000 nodes, D=64, E=800000 edges, P=2.
//
// R9: harness targets sm_100 (no 'a') -> tcgen05 unavailable. Edge-MLP GEMMs
// now use warp-level mma.sync.m16n8k16 bf16 (HMMA) with ldmatrix fragment
// loads from SW128-swizzled smem, bf16 hi+lo 3-term split for fp32 accuracy.
// 384 threads, 192-edge tiles; each warp owns 16 edges x 64 outputs in regs;
// epilogues warp-local (2 block barriers per tile total).
// ---------------------------------------------------------------------------

typedef unsigned long long ull;

#define MAXN 50000
#define MAXD 64
#define MAXE 800000

// scratch (device globals: allocation-free rule)
__device__ __align__(16) float d_hsum[MAXN * MAXD];
__device__ __align__(16) float d_agg[MAXN * MAXD];
__device__ __align__(16) float d_posacc[MAXN * 2];
__device__ float d_deg[MAXN];
__device__ int   d_src[MAXE];
__device__ int   d_dst[MAXE];
__device__ int   d_e32flag;   // 1 if edge_index buffer is int32, 0 if int64

// ---- small helpers ----------------------------------------------------------
__device__ __forceinline__ uint32_t smem_to_u32(const void* p) {
    uint32_t a;
    asm("{ .reg .u64 t; cvta.to.shared.u64 t, %1; cvt.u32.u64 %0, t; }"
        : "=r"(a) : "l"(p));
    return a;
}
__device__ __forceinline__ float silu_f(float x) {
    return x / (1.0f + __expf(-x));
}
__device__ __forceinline__ void red_add_v2(float* p, float x, float y) {
    asm volatile("red.global.add.v2.f32 [%0], {%1, %2};"
                 :: "l"(p), "f"(x), "f"(y) : "memory");
}
__device__ __forceinline__ ull pk2(float lo, float hi) {
    ull r; asm("mov.b64 %0, {%1,%2};" : "=l"(r) : "f"(lo), "f"(hi)); return r;
}
__device__ __forceinline__ void upk2(ull v, float& lo, float& hi) {
    asm("mov.b64 {%0,%1}, %2;" : "=f"(lo), "=f"(hi) : "l"(v));
}
__device__ __forceinline__ ull fma2(ull a, ull b, ull c) {
    ull d; asm("fma.rn.f32x2 %0, %1, %2, %3;" : "=l"(d) : "l"(a), "l"(b), "l"(c));
    return d;
}

// ---- mma / ldmatrix primitives (sm_80-compatible, run on sm_100 HMMA) -------
__device__ __forceinline__ void ldsm_x4(uint32_t& r0, uint32_t& r1,
                                        uint32_t& r2, uint32_t& r3, uint32_t addr) {
    asm volatile("ldmatrix.sync.aligned.m8n8.x4.shared.b16 {%0,%1,%2,%3}, [%4];"
                 : "=r"(r0), "=r"(r1), "=r"(r2), "=r"(r3) : "r"(addr));
}
__device__ __forceinline__ void mma_bf16(float* c,
                                         uint32_t a0, uint32_t a1, uint32_t a2, uint32_t a3,
                                         uint32_t b0, uint32_t b1) {
    asm volatile("mma.sync.aligned.m16n8k16.row.col.f32.bf16.bf16.f32 "
                 "{%0,%1,%2,%3}, {%4,%5,%6,%7}, {%8,%9}, {%0,%1,%2,%3};"
                 : "+f"(c[0]), "+f"(c[1]), "+f"(c[2]), "+f"(c[3])
                 : "r"(a0), "r"(a1), "r"(a2), "r"(a3), "r"(b0), "r"(b1));
}

// lane-specific ldmatrix.x4 address into a [rows x 64 bf16] SW128 plane
// (row stride 128B, 16B-granule XOR swizzle ((row&7)<<4)).
// Quad mapping: q0: rows+0 k+0 | q1: rows+8 k+0 | q2: rows+0 k+8 | q3: rows+8 k+8
// -> regs match mma A-frag {a0,a1,a2,a3} and B-frag pairs.
__device__ __forceinline__ uint32_t lds_addr(uint32_t base, int rowbase, int kc, int lane) {
    const int quad = lane >> 3, r8 = lane & 7;
    const int row = rowbase + r8 + (quad & 1) * 8;
    const int kb = kc * 32 + (quad >> 1) * 16;
    return base + row * 128 + (kb ^ ((row & 7) << 4));
}

// ---- bf16 hi/lo split helpers ------------------------------------------------
__device__ __forceinline__ uint32_t pack_bf2(float x, float y) {
    __nv_bfloat162 h = __floats2bfloat162_rn(x, y);
    return *reinterpret_cast<uint32_t*>(&h);
}
__device__ __forceinline__ float2 unpack_bf2(uint32_t u) {
    __nv_bfloat162 h = *reinterpret_cast<__nv_bfloat162*>(&u);
    return __bfloat1622float2(h);
}
__device__ __forceinline__ void cvt_hilo(const float4 a, const float4 b,
                                         uint4& hi, uint4& lo) {
    const uint32_t h0 = pack_bf2(a.x, a.y);
    const uint32_t h1 = pack_bf2(a.z, a.w);
    const uint32_t h2 = pack_bf2(b.x, b.y);
    const uint32_t h3 = pack_bf2(b.z, b.w);
    const float2 f0 = unpack_bf2(h0), f1 = unpack_bf2(h1);
    const float2 f2 = unpack_bf2(h2), f3 = unpack_bf2(h3);
    lo.x = pack_bf2(a.x - f0.x, a.y - f0.y);
    lo.y = pack_bf2(a.z - f1.x, a.w - f1.y);
    lo.z = pack_bf2(b.x - f2.x, b.y - f2.y);
    lo.w = pack_bf2(b.z - f3.x, b.w - f3.y);
    hi = make_uint4(h0, h1, h2, h3);
}
__device__ __forceinline__ void stage_pair(char* hip, char* lop, float v) {
    __nv_bfloat16 h = __float2bfloat16_rn(v);
    float r = v - __bfloat162float(h);
    __nv_bfloat16 l = __float2bfloat16_rn(r);
    *reinterpret_cast<__nv_bfloat16*>(hip) = h;
    *reinterpret_cast<__nv_bfloat16*>(lop) = l;
}
// hi/lo pair store for two adjacent values
__device__ __forceinline__ void stage_pair2(char* hip, char* lop, float v0, float v1) {
    const uint32_t hi = pack_bf2(v0, v1);
    const float2 f = unpack_bf2(hi);
    const uint32_t lo = pack_bf2(v0 - f.x, v1 - f.y);
    *reinterpret_cast<uint32_t*>(hip) = hi;
    *reinterpret_cast<uint32_t*>(lop) = lo;
}

// ---- edge kernel config ------------------------------------------------------
constexpr int TILE_E   = 192;               // edges per tile (12 warps x 16)
constexpr int NTHREADS = 384;

// smem byte offsets
constexpr int OFF_SIDX = 0;                 // 384 ints (dst[192], src[192])
constexpr int OFF_D2   = 1536;              // 192 f32
constexpr int OFF_REL  = 2304;              // 384 f32
constexpr int OFF_B1   = 3840;              // 64 f32 each below
constexpr int OFF_B2   = 4096;
constexpr int OFF_BP1  = 4352;
constexpr int OFF_W1C  = 4608;              // W_msg1 row 128 (d2 rank-1)
constexpr int OFF_WP2  = 4864;
constexpr int OFF_BP2  = 5120;
// weight B-tiles [n=64][k=64] bf16 SW128 (8KB each)
constexpr int OFF_B1A_HI = 8192;
constexpr int OFF_B1A_LO = 16384;
constexpr int OFF_B1B_HI = 24576;
constexpr int OFF_B1B_LO = 32768;
constexpr int OFF_B2_HI  = 40960;
constexpr int OFF_B2_LO  = 49152;
constexpr int OFF_BP1_HI = 57344;
constexpr int OFF_BP1_LO = 65536;
// A-tiles [192 x 64] bf16 SW128 (24KB each)
constexpr int OFF_ADST_HI = 73728;
constexpr int OFF_ADST_LO = 98304;
constexpr int OFF_ASRC_HI = 122880;
constexpr int OFF_ASRC_LO = 147456;
// activation tile t1/m [192 x 64] bf16 hi/lo
constexpr int OFF_T_HI = 172032;
constexpr int OFF_T_LO = 196608;
constexpr int EDGE_SMEM_BYTES = 221184;     // 216 KB

// ---- node kernel smem layout (floats) ----------------------------------------
constexpr int NS_WH1 = 0;
constexpr int NS_WH2 = 8192;
constexpr int NS_BH1 = 12288;
constexpr int NS_BH2 = 12352;
constexpr int NS_X   = 12416;
constexpr int NS_Y   = 12928;
constexpr int NODE_SMEM_BYTES = (NS_Y + 256) * 4;

// ---------------------------------------------------------------------------
// One 3-term GEMM pass over K=64: acc += Ah*Bh + Ah*Bl + Al*Bh
// (warp-level; A rows = rowbase..rowbase+15, all 64 output cols)
// ---------------------------------------------------------------------------
__device__ __forceinline__ void gemm_term_pass(
    float acc[8][4],
    uint32_t aHi, uint32_t aLo, uint32_t bHi, uint32_t bLo,
    int rowbase, int lane)
{
#pragma unroll
    for (int kc = 0; kc < 4; ++kc) {
        uint32_t ah[4], al[4], bh[16], bl[16];
        ldsm_x4(ah[0], ah[1], ah[2], ah[3], lds_addr(aHi, rowbase, kc, lane));
        ldsm_x4(al[0], al[1], al[2], al[3], lds_addr(aLo, rowbase, kc, lane));
#pragma unroll
        for (int p = 0; p < 4; ++p) {
            ldsm_x4(bh[4*p], bh[4*p+1], bh[4*p+2], bh[4*p+3], lds_addr(bHi, 16*p, kc, lane));
            ldsm_x4(bl[4*p], bl[4*p+1], bl[4*p+2], bl[4*p+3], lds_addr(bLo, 16*p, kc, lane));
        }
#pragma unroll
        for (int nt = 0; nt < 8; ++nt) {
            const int p = nt >> 1, o = nt & 1;
            mma_bf16(acc[nt], ah[0], ah[1], ah[2], ah[3], bh[4*p+o], bh[4*p+2+o]);
        }
#pragma unroll
        for (int nt = 0; nt < 8; ++nt) {
            const int p = nt >> 1, o = nt & 1;
            mma_bf16(acc[nt], ah[0], ah[1], ah[2], ah[3], bl[4*p+o], bl[4*p+2+o]);
        }
#pragma unroll
        for (int nt = 0; nt < 8; ++nt) {
            const int p = nt >> 1, o = nt & 1;
            mma_bf16(acc[nt], al[0], al[1], al[2], al[3], bh[4*p+o], bh[4*p+2+o]);
        }
    }
}

// ---------------------------------------------------------------------------
// Kernel 0a/0b: edge_index dtype detect + normalize.
// ---------------------------------------------------------------------------
__global__ void egnn_detect_kernel(const long long* __restrict__ ei, const int E)
{
    __shared__ int bad;
    if (threadIdx.x == 0) bad = 0;
    __syncthreads();
    const int cnt = E < 1024 ? E : 1024;
    for (int i = threadIdx.x; i < cnt; i += blockDim.x) {
        const long long v = ei[i];
        if (v < 0 || v > 0x7FFFFFFFLL) bad = 1;
    }
    __syncthreads();
    if (threadIdx.x == 0) d_e32flag = bad;
}

__global__ void egnn_cvt_kernel(const void* __restrict__ ei, const int E)
{
    const int i = blockIdx.x * blockDim.x + threadIdx.x;
    if (i >= 2 * E) return;
    int v;
    if (d_e32flag) v = ((const int*)ei)[i];
    else           v = (int)(((const long long*)ei)[i]);
    if (i < E) d_src[i] = v;
    else       d_dst[i - E] = v;
}

// ---------------------------------------------------------------------------
// Kernel 1: hsum = h + h_init; zero accumulators.
// ---------------------------------------------------------------------------
__global__ void egnn_init_kernel(const float* __restrict__ h,
                                 const float* __restrict__ hi, const int N)
{
    const int i = blockIdx.x * blockDim.x + threadIdx.x;
    const int n4 = N * 16;
    if (i < n4) {
        const float4 a = reinterpret_cast<const float4*>(h)[i];
        const float4 b = reinterpret_cast<const float4*>(hi)[i];
        float4 s;
        s.x = a.x + b.x; s.y = a.y + b.y; s.z = a.z + b.z; s.w = a.w + b.w;
        reinterpret_cast<float4*>(d_hsum)[i] = s;
        reinterpret_cast<float4*>(d_agg)[i] = make_float4(0.f, 0.f, 0.f, 0.f);
    }
    if (i < N) d_deg[i] = 0.0f;
    if (i < N * 2) d_posacc[i] = 0.0f;
}

// ---------------------------------------------------------------------------
// Kernel 2: persistent mma.sync edge kernel. 384 threads; 192-edge tiles.
// ---------------------------------------------------------------------------
__global__ void __launch_bounds__(NTHREADS, 1)
egnn_edge_kernel(const float* __restrict__ pos,
                 const float* __restrict__ Wm1, const float* __restrict__ bm1,
                 const float* __restrict__ Wm2, const float* __restrict__ bm2,
                 const float* __restrict__ Wp1, const float* __restrict__ bp1,
                 const float* __restrict__ Wp2, const float* __restrict__ bp2,
                 const int E, const int N)
{
    extern __shared__ char smem[];
    const uint32_t su = smem_to_u32(smem);
    const int tid = threadIdx.x;
    const int wid = tid >> 5;
    const int lane = tid & 31;

    // ---- stage weights as bf16 hi/lo B-tiles (B[n][k] = W[k][n], SW128) ----
    for (int idx = tid; idx < 4096; idx += NTHREADS) {
        const int n = idx >> 6, k = idx & 63;
        const int off = n * 128 + ((k * 2) ^ ((n & 7) << 4));
        stage_pair(smem + OFF_B1A_HI + off, smem + OFF_B1A_LO + off, Wm1[k * 64 + n]);
        stage_pair(smem + OFF_B1B_HI + off, smem + OFF_B1B_LO + off, Wm1[(64 + k) * 64 + n]);
        stage_pair(smem + OFF_B2_HI  + off, smem + OFF_B2_LO  + off, Wm2[k * 64 + n]);
        stage_pair(smem + OFF_BP1_HI + off, smem + OFF_BP1_LO + off, Wp1[k * 64 + n]);
    }
    if (tid < 64) {
        ((float*)(smem + OFF_B1 ))[tid] = bm1[tid];
        ((float*)(smem + OFF_B2 ))[tid] = bm2[tid];
        ((float*)(smem + OFF_BP1))[tid] = bp1[tid];
        ((float*)(smem + OFF_W1C))[tid] = Wm1[128 * 64 + tid];
        ((float*)(smem + OFF_WP2))[tid] = Wp2[tid];
    }
    if (tid == 0) ((float*)(smem + OFF_BP2))[0] = bp2[0];
    __syncthreads();

    int* sidx   = (int*)(smem + OFF_SIDX);   // [0..191]=dst, [192..383]=src
    float* sd2  = (float*)(smem + OFF_D2);
    float* srel = (float*)(smem + OFF_REL);
    const float* sb1  = (const float*)(smem + OFF_B1);
    const float* sb2  = (const float*)(smem + OFF_B2);
    const float* sbp1 = (const float*)(smem + OFF_BP1);
    const float* sw1c = (const float*)(smem + OFF_W1C);
    const float* swp2 = (const float*)(smem + OFF_WP2);

    const int rowbase = wid * 16;         // this warp's 16 edges within tile
    const int l4 = lane & 3;
    const int rgrp = lane >> 2;
    const int r0 = rowbase + rgrp;        // accum rows for this lane
    const int r1 = r0 + 8;

    const int nTiles = (E + TILE_E - 1) / TILE_E;

    for (int t = blockIdx.x; t < nTiles; t += gridDim.x) {
        const int eBase = t * TILE_E;
        const int erow = (tid < TILE_E) ? tid : (tid - TILE_E);

        __syncthreads();   // previous tile fully consumed before overwrite

        // ---- indices + gather: one hsum row per thread -> bf16 hi/lo row ----
        {
            const int e = eBase + erow;
            int node = -1;
            if (e < E) node = (tid < TILE_E) ? d_dst[e] : d_src[e];
            if ((unsigned)node >= (unsigned)N) node = -1;
            sidx[tid] = node;

            char* hiT = smem + (tid < TILE_E ? OFF_ADST_HI : OFF_ASRC_HI);
            char* loT = smem + (tid < TILE_E ? OFF_ADST_LO : OFF_ASRC_LO);
            const float4* srcp =
                reinterpret_cast<const float4*>(d_hsum) + (size_t)(node < 0 ? 0 : node) * 16;
#pragma unroll
            for (int i = 0; i < 8; ++i) {
                float4 a = make_float4(0.f, 0.f, 0.f, 0.f), b = a;
                if (node >= 0) { a = srcp[2 * i]; b = srcp[2 * i + 1]; }
                uint4 hi, lo;
                cvt_hilo(a, b, hi, lo);
                const int off = erow * 128 + ((i * 16) ^ ((erow & 7) << 4));
                *reinterpret_cast<uint4*>(hiT + off) = hi;
                *reinterpret_cast<uint4*>(loT + off) = lo;
            }
        }
        __syncthreads();   // publish sidx + A planes

        if (tid < TILE_E) {   // rel/d2 (after sidx is published)
            const int dn = sidx[tid], sn = sidx[TILE_E + tid];
            float rx = 0.f, ry = 0.f;
            if (dn >= 0 && sn >= 0) {
                const float2 pd = reinterpret_cast<const float2*>(pos)[dn];
                const float2 ps = reinterpret_cast<const float2*>(pos)[sn];
                rx = pd.x - ps.x; ry = pd.y - ps.y;
            }
            srel[2 * tid] = rx; srel[2 * tid + 1] = ry;
            sd2[tid] = rx * rx + ry * ry;
        }
        __syncthreads();

        float acc[8][4];

        // ================= GEMM1: t1 = silu(m_in @ W1 + d2*w1c + b1) =========
#pragma unroll
        for (int nt = 0; nt < 8; ++nt)
#pragma unroll
            for (int j = 0; j < 4; ++j) acc[nt][j] = 0.f;

        gemm_term_pass(acc, su + OFF_ADST_HI, su + OFF_ADST_LO,
                       su + OFF_B1A_HI, su + OFF_B1A_LO, rowbase, lane);
        gemm_term_pass(acc, su + OFF_ASRC_HI, su + OFF_ASRC_LO,
                       su + OFF_B1B_HI, su + OFF_B1B_LO, rowbase, lane);

        {   // epilogue 1: bias + d2 rank-1 + silu, restage hi/lo into T
            const float dd0 = sd2[r0], dd1 = sd2[r1];
            const int sw0 = (r0 & 7) << 4, sw1 = (r1 & 7) << 4;
#pragma unroll
            for (int nt = 0; nt < 8; ++nt) {
                const int cb = nt * 8 + 2 * l4;
                const float w0 = sw1c[cb], w1 = sw1c[cb + 1];
                const float bb0 = sb1[cb], bb1 = sb1[cb + 1];
                const float v0 = silu_f(acc[nt][0] + dd0 * w0 + bb0);
                const float v1 = silu_f(acc[nt][1] + dd0 * w1 + bb1);
                const float v2 = silu_f(acc[nt][2] + dd1 * w0 + bb0);
                const float v3 = silu_f(acc[nt][3] + dd1 * w1 + bb1);
                const int o0 = r0 * 128 + ((nt * 16) ^ sw0) + 4 * l4;
                const int o1 = r1 * 128 + ((nt * 16) ^ sw1) + 4 * l4;
                stage_pair2(smem + OFF_T_HI + o0, smem + OFF_T_LO + o0, v0, v1);
                stage_pair2(smem + OFF_T_HI + o1, smem + OFF_T_LO + o1, v2, v3);
            }
        }
        __syncwarp();

        // ================= GEMM2: m = silu(t1 @ W2 + b2) ======================
#pragma unroll
        for (int nt = 0; nt < 8; ++nt)
#pragma unroll
            for (int j = 0; j < 4; ++j) acc[nt][j] = 0.f;

        gemm_term_pass(acc, su + OFF_T_HI, su + OFF_T_LO,
                       su + OFF_B2_HI, su + OFF_B2_LO, rowbase, lane);
        __syncwarp();   // all T reads done before restage

        {   // epilogue 2: silu, scatter agg (red.v2), restage m into T
            const int dn0 = sidx[r0], dn1 = sidx[r1];
            float* agg0 = d_agg + (size_t)(dn0 < 0 ? 0 : dn0) * 64;
            float* agg1 = d_agg + (size_t)(dn1 < 0 ? 0 : dn1) * 64;
            const int sw0 = (r0 & 7) << 4, sw1 = (r1 & 7) << 4;
#pragma unroll
            for (int nt = 0; nt < 8; ++nt) {
                const int cb = nt * 8 + 2 * l4;
                const float bb0 = sb2[cb], bb1 = sb2[cb + 1];
                const float v0 = silu_f(acc[nt][0] + bb0);
                const float v1 = silu_f(acc[nt][1] + bb1);
                const float v2 = silu_f(acc[nt][2] + bb0);
                const float v3 = silu_f(acc[nt][3] + bb1);
                if (dn0 >= 0) red_add_v2(agg0 + cb, v0, v1);
                if (dn1 >= 0) red_add_v2(agg1 + cb, v2, v3);
                const int o0 = r0 * 128 + ((nt * 16) ^ sw0) + 4 * l4;
                const int o1 = r1 * 128 + ((nt * 16) ^ sw1) + 4 * l4;
                stage_pair2(smem + OFF_T_HI + o0, smem + OFF_T_LO + o0, v0, v1);
                stage_pair2(smem + OFF_T_HI + o1, smem + OFF_T_LO + o1, v2, v3);
            }
        }
        __syncwarp();

        // ============ GEMM3: w = silu(m @ Wp1 + bp1) . Wp2 + bp2 ==============
#pragma unroll
        for (int nt = 0; nt < 8; ++nt)
#pragma unroll
            for (int j = 0; j < 4; ++j) acc[nt][j] = 0.f;

        gemm_term_pass(acc, su + OFF_T_HI, su + OFF_T_LO,
                       su + OFF_BP1_HI, su + OFF_BP1_LO, rowbase, lane);

        {   // epilogue 3: per-row dot with Wp2, 4-lane reduce, pos scatter
            float p0 = 0.f, p1 = 0.f;
#pragma unroll
            for (int nt = 0; nt < 8; ++nt) {
                const int cb = nt * 8 + 2 * l4;
                const float bb0 = sbp1[cb], bb1 = sbp1[cb + 1];
                const float w0 = swp2[cb], w1 = swp2[cb + 1];
                p0 += silu_f(acc[nt][0] + bb0) * w0 + silu_f(acc[nt][1] + bb1) * w1;
                p1 += silu_f(acc[nt][2] + bb0) * w0 + silu_f(acc[nt][3] + bb1) * w1;
            }
            p0 += __shfl_xor_sync(0xFFFFFFFFu, p0, 1);
            p0 += __shfl_xor_sync(0xFFFFFFFFu, p0, 2);
            p1 += __shfl_xor_sync(0xFFFFFFFFu, p1, 1);
            p1 += __shfl_xor_sync(0xFFFFFFFFu, p1, 2);
            if (l4 == 0) {
                const float bp2v = ((const float*)(smem + OFF_BP2))[0];
                const int dn0 = sidx[r0], dn1 = sidx[r1];
                if (dn0 >= 0) {
                    const float w = p0 + bp2v;
                    red_add_v2(&d_posacc[dn0 * 2], srel[2 * r0] * w, srel[2 * r0 + 1] * w);
                    atomicAdd(&d_deg[dn0], 1.0f);
                }
                if (dn1 >= 0) {
                    const float w = p1 + bp2v;
                    red_add_v2(&d_posacc[dn1 * 2], srel[2 * r1] * w, srel[2 * r1 + 1] * w);
                    atomicAdd(&d_deg[dn1], 1.0f);
                }
            }
        }
    }
}

// ---------------------------------------------------------------------------
// Kernel 3: node update (phi_h) + skip connections + pos update. Warp/node.
// ---------------------------------------------------------------------------
__global__ void __launch_bounds__(128, 4)
egnn_node_kernel(const float* __restrict__ pos,
                 const float* __restrict__ Wh1, const float* __restrict__ bh1,
                 const float* __restrict__ Wh2, const float* __restrict__ bh2,
                 float* __restrict__ out, const int N)
{
    extern __shared__ float sm[];
    const int tid = threadIdx.x;

    for (int i = tid; i < 8192; i += 128) sm[NS_WH1 + i] = Wh1[i];
    for (int i = tid; i < 4096; i += 128) sm[NS_WH2 + i] = Wh2[i];
    if (tid < 64) {
        sm[NS_BH1 + tid] = bh1[tid];
        sm[NS_BH2 + tid] = bh2[tid];
    }
    __syncthreads();

    const int w = tid >> 5, lane = tid & 31;
    float* sx = sm + NS_X + w * 128;
    float* sy = sm + NS_Y + w * 64;
    const float bb10 = sm[NS_BH1 + 2 * lane], bb11 = sm[NS_BH1 + 2 * lane + 1];
    const float bb20 = sm[NS_BH2 + 2 * lane], bb21 = sm[NS_BH2 + 2 * lane + 1];

    const int gw = blockIdx.x * 4 + w;
    const int nw = gridDim.x * 4;
    float* out_pos = out + (long long)N * 64;

    for (int n = gw; n < N; n += nw) {
        sx[lane]      = d_hsum[n * 64 + lane];
        sx[32 + lane] = d_hsum[n * 64 + 32 + lane];
        sx[64 + lane] = d_agg[n * 64 + lane];
        sx[96 + lane] = d_agg[n * 64 + 32 + lane];
        __syncwarp();

        ull acc = 0ULL;
#pragma unroll 4
        for (int i = 0; i < 128; ++i) {
            const float a = sx[i];
            const ull b = reinterpret_cast<const ull*>(sm + NS_WH1 + i * 64)[lane];
            acc = fma2(pk2(a, a), b, acc);
        }
        float y0, y1;
        upk2(acc, y0, y1);
        y0 = silu_f(y0 + bb10);
        y1 = silu_f(y1 + bb11);
        *reinterpret_cast<float2*>(sy + 2 * lane) = make_float2(y0, y1);
        __syncwarp();

        acc = 0ULL;
#pragma unroll 4
        for (int i = 0; i < 64; ++i) {
            const float a = sy[i];
            const ull b = reinterpret_cast<const ull*>(sm + NS_WH2 + i * 64)[lane];
            acc = fma2(pk2(a, a), b, acc);
        }
        float o0, o1;
        upk2(acc, o0, o1);
        o0 += bb20 + sx[2 * lane];
        o1 += bb21 + sx[2 * lane + 1];
        *reinterpret_cast<float2*>(out + (long long)n * 64 + 2 * lane) = make_float2(o0, o1);

        if (lane < 2) {
            const float dg = fmaxf(d_deg[n], 1.0f);
            out_pos[n * 2 + lane] = pos[n * 2 + lane] + d_posacc[n * 2 + lane] / dg;
        }
        __syncwarp();
    }
}

// ---------------------------------------------------------------------------
extern "C" void kernel_launch(void* const* d_in, const int* in_sizes, int n_in,
                              void* d_out, int out_size)
{
    const float* h      = (const float*)d_in[0];
    const float* pos    = (const float*)d_in[1];
    const float* h_init = (const float*)d_in[2];
    const float* Wm1    = (const float*)d_in[3];
    const float* bm1    = (const float*)d_in[4];
    const float* Wm2    = (const float*)d_in[5];
    const float* bm2    = (const float*)d_in[6];
    const float* Wp1    = (const float*)d_in[7];
    const float* bp1    = (const float*)d_in[8];
    const float* Wp2    = (const float*)d_in[9];
    const float* bp2    = (const float*)d_in[10];
    const float* Wh1    = (const float*)d_in[11];
    const float* bh1    = (const float*)d_in[12];
    const float* Wh2    = (const float*)d_in[13];
    const float* bh2    = (const float*)d_in[14];
    const void*  ei     = d_in[15];

    const int N = in_sizes[0] / 64;
    const int E = in_sizes[15] / 2;
    float* out = (float*)d_out;

    cudaFuncSetAttribute(egnn_edge_kernel,
                         cudaFuncAttributeMaxDynamicSharedMemorySize, EDGE_SMEM_BYTES);
    cudaFuncSetAttribute(egnn_node_kernel,
                         cudaFuncAttributeMaxDynamicSharedMemorySize, NODE_SMEM_BYTES);

    egnn_detect_kernel<<<1, 256>>>((const long long*)ei, E);
    egnn_cvt_kernel<<<(2 * E + 255) / 256, 256>>>(ei, E);
    egnn_init_kernel<<<(N * 16 + 255) / 256, 256>>>(h, h_init, N);

    const int nTiles = (E + TILE_E - 1) / TILE_E;
    int eblocks = nTiles < 148 ? nTiles : 148;
    egnn_edge_kernel<<<eblocks, NTHREADS, EDGE_SMEM_BYTES>>>(
        pos, Wm1, bm1, Wm2, bm2, Wp1, bp1, Wp2, bp2, E, N);

    egnn_node_kernel<<<592, 128, NODE_SMEM_BYTES>>>(pos, Wh1, bh1, Wh2, bh2, out, N);
}

// round 10
// speedup vs baseline: 2.3218x; 1.0796x over previous
#include <cuda_runtime.h>
#include <cuda_bf16.h>
#include <stdint.h>

// ---------------------------------------------------------------------------
// EGNN / SpatialNCA step.  N=50000 nodes, D=64, E=800000 edges, P=2.
//
// R10: occupancy push on the mma.sync edge kernel.
//  - T activation tile aliases the A-dst planes (each warp touches only its
//    own 16 rows through the whole GEMM chain -> in-place reuse is safe).
//  - 512 threads / 16 warps, 256-edge tiles (smem 200 KB, 1 CTA/SM, occ 25%).
//  - 2 block barriers per tile (rel/d2 folded into gather via direct d_src).
// ---------------------------------------------------------------------------

typedef unsigned long long ull;

#define MAXN 50000
#define MAXD 64
#define MAXE 800000

// scratch (device globals: allocation-free rule)
__device__ __align__(16) float d_hsum[MAXN * MAXD];
__device__ __align__(16) float d_agg[MAXN * MAXD];
__device__ __align__(16) float d_posacc[MAXN * 2];
__device__ float d_deg[MAXN];
__device__ int   d_src[MAXE];
__device__ int   d_dst[MAXE];
__device__ int   d_e32flag;   // 1 if edge_index buffer is int32, 0 if int64

// ---- small helpers ----------------------------------------------------------
__device__ __forceinline__ uint32_t smem_to_u32(const void* p) {
    uint32_t a;
    asm("{ .reg .u64 t; cvta.to.shared.u64 t, %1; cvt.u32.u64 %0, t; }"
        : "=r"(a) : "l"(p));
    return a;
}
__device__ __forceinline__ float silu_f(float x) {
    return x / (1.0f + __expf(-x));
}
__device__ __forceinline__ void red_add_v2(float* p, float x, float y) {
    asm volatile("red.global.add.v2.f32 [%0], {%1, %2};"
                 :: "l"(p), "f"(x), "f"(y) : "memory");
}
__device__ __forceinline__ ull pk2(float lo, float hi) {
    ull r; asm("mov.b64 %0, {%1,%2};" : "=l"(r) : "f"(lo), "f"(hi)); return r;
}
__device__ __forceinline__ void upk2(ull v, float& lo, float& hi) {
    asm("mov.b64 {%0,%1}, %2;" : "=f"(lo), "=f"(hi) : "l"(v));
}
__device__ __forceinline__ ull fma2(ull a, ull b, ull c) {
    ull d; asm("fma.rn.f32x2 %0, %1, %2, %3;" : "=l"(d) : "l"(a), "l"(b), "l"(c));
    return d;
}

// ---- mma / ldmatrix primitives (sm_80-compatible, run on sm_100 HMMA) -------
__device__ __forceinline__ void ldsm_x4(uint32_t& r0, uint32_t& r1,
                                        uint32_t& r2, uint32_t& r3, uint32_t addr) {
    asm volatile("ldmatrix.sync.aligned.m8n8.x4.shared.b16 {%0,%1,%2,%3}, [%4];"
                 : "=r"(r0), "=r"(r1), "=r"(r2), "=r"(r3) : "r"(addr));
}
__device__ __forceinline__ void mma_bf16(float* c,
                                         uint32_t a0, uint32_t a1, uint32_t a2, uint32_t a3,
                                         uint32_t b0, uint32_t b1) {
    asm volatile("mma.sync.aligned.m16n8k16.row.col.f32.bf16.bf16.f32 "
                 "{%0,%1,%2,%3}, {%4,%5,%6,%7}, {%8,%9}, {%0,%1,%2,%3};"
                 : "+f"(c[0]), "+f"(c[1]), "+f"(c[2]), "+f"(c[3])
                 : "r"(a0), "r"(a1), "r"(a2), "r"(a3), "r"(b0), "r"(b1));
}

// lane-specific ldmatrix.x4 address into a [rows x 64 bf16] SW128 plane
// (row stride 128B, 16B-granule XOR swizzle ((row&7)<<4)).
__device__ __forceinline__ uint32_t lds_addr(uint32_t base, int rowbase, int kc, int lane) {
    const int quad = lane >> 3, r8 = lane & 7;
    const int row = rowbase + r8 + (quad & 1) * 8;
    const int kb = kc * 32 + (quad >> 1) * 16;
    return base + row * 128 + (kb ^ ((row & 7) << 4));
}

// ---- bf16 hi/lo split helpers ------------------------------------------------
__device__ __forceinline__ uint32_t pack_bf2(float x, float y) {
    __nv_bfloat162 h = __floats2bfloat162_rn(x, y);
    return *reinterpret_cast<uint32_t*>(&h);
}
__device__ __forceinline__ float2 unpack_bf2(uint32_t u) {
    __nv_bfloat162 h = *reinterpret_cast<__nv_bfloat162*>(&u);
    return __bfloat1622float2(h);
}
__device__ __forceinline__ void cvt_hilo(const float4 a, const float4 b,
                                         uint4& hi, uint4& lo) {
    const uint32_t h0 = pack_bf2(a.x, a.y);
    const uint32_t h1 = pack_bf2(a.z, a.w);
    const uint32_t h2 = pack_bf2(b.x, b.y);
    const uint32_t h3 = pack_bf2(b.z, b.w);
    const float2 f0 = unpack_bf2(h0), f1 = unpack_bf2(h1);
    const float2 f2 = unpack_bf2(h2), f3 = unpack_bf2(h3);
    lo.x = pack_bf2(a.x - f0.x, a.y - f0.y);
    lo.y = pack_bf2(a.z - f1.x, a.w - f1.y);
    lo.z = pack_bf2(b.x - f2.x, b.y - f2.y);
    lo.w = pack_bf2(b.z - f3.x, b.w - f3.y);
    hi = make_uint4(h0, h1, h2, h3);
}
__device__ __forceinline__ void stage_pair(char* hip, char* lop, float v) {
    __nv_bfloat16 h = __float2bfloat16_rn(v);
    float r = v - __bfloat162float(h);
    __nv_bfloat16 l = __float2bfloat16_rn(r);
    *reinterpret_cast<__nv_bfloat16*>(hip) = h;
    *reinterpret_cast<__nv_bfloat16*>(lop) = l;
}
__device__ __forceinline__ void stage_pair2(char* hip, char* lop, float v0, float v1) {
    const uint32_t hi = pack_bf2(v0, v1);
    const float2 f = unpack_bf2(hi);
    const uint32_t lo = pack_bf2(v0 - f.x, v1 - f.y);
    *reinterpret_cast<uint32_t*>(hip) = hi;
    *reinterpret_cast<uint32_t*>(lop) = lo;
}

// ---- edge kernel config ------------------------------------------------------
constexpr int TILE_E   = 256;               // edges per tile (16 warps x 16)
constexpr int NTHREADS = 512;

// smem byte offsets
constexpr int OFF_SIDX = 0;                 // 512 ints (dst[256], src[256])
constexpr int OFF_D2   = 2048;              // 256 f32
constexpr int OFF_REL  = 3072;              // 512 f32
constexpr int OFF_B1   = 5120;              // 64 f32 each below
constexpr int OFF_B2   = 5376;
constexpr int OFF_BP1  = 5632;
constexpr int OFF_W1C  = 5888;              // W_msg1 row 128 (d2 rank-1)
constexpr int OFF_WP2  = 6144;
constexpr int OFF_BP2  = 6400;
// weight B-tiles [n=64][k=64] bf16 SW128 (8KB each)
constexpr int OFF_B1A_HI = 8192;
constexpr int OFF_B1A_LO = 16384;
constexpr int OFF_B1B_HI = 24576;
constexpr int OFF_B1B_LO = 32768;
constexpr int OFF_B2_HI  = 40960;
constexpr int OFF_B2_LO  = 49152;
constexpr int OFF_BP1_HI = 57344;
constexpr int OFF_BP1_LO = 65536;
// A-tiles [256 x 64] bf16 SW128 (32KB each)
constexpr int OFF_ADST_HI = 73728;
constexpr int OFF_ADST_LO = 106496;
constexpr int OFF_ASRC_HI = 139264;
constexpr int OFF_ASRC_LO = 172032;
// activation tile t1/m ALIASES the A-dst planes (warp-private row reuse)
constexpr int OFF_T_HI = OFF_ADST_HI;
constexpr int OFF_T_LO = OFF_ADST_LO;
constexpr int EDGE_SMEM_BYTES = 204800;     // 200 KB

// ---- node kernel smem layout (floats) ----------------------------------------
constexpr int NS_WH1 = 0;
constexpr int NS_WH2 = 8192;
constexpr int NS_BH1 = 12288;
constexpr int NS_BH2 = 12352;
constexpr int NS_X   = 12416;
constexpr int NS_Y   = 12928;
constexpr int NODE_SMEM_BYTES = (NS_Y + 256) * 4;

// ---------------------------------------------------------------------------
// One 3-term GEMM pass over K=64: acc += Ah*Bh + Ah*Bl + Al*Bh
// ---------------------------------------------------------------------------
__device__ __forceinline__ void gemm_term_pass(
    float acc[8][4],
    uint32_t aHi, uint32_t aLo, uint32_t bHi, uint32_t bLo,
    int rowbase, int lane)
{
#pragma unroll
    for (int kc = 0; kc < 4; ++kc) {
        uint32_t ah[4], al[4], bh[16], bl[16];
        ldsm_x4(ah[0], ah[1], ah[2], ah[3], lds_addr(aHi, rowbase, kc, lane));
        ldsm_x4(al[0], al[1], al[2], al[3], lds_addr(aLo, rowbase, kc, lane));
#pragma unroll
        for (int p = 0; p < 4; ++p) {
            ldsm_x4(bh[4*p], bh[4*p+1], bh[4*p+2], bh[4*p+3], lds_addr(bHi, 16*p, kc, lane));
            ldsm_x4(bl[4*p], bl[4*p+1], bl[4*p+2], bl[4*p+3], lds_addr(bLo, 16*p, kc, lane));
        }
#pragma unroll
        for (int nt = 0; nt < 8; ++nt) {
            const int p = nt >> 1, o = nt & 1;
            mma_bf16(acc[nt], ah[0], ah[1], ah[2], ah[3], bh[4*p+o], bh[4*p+2+o]);
        }
#pragma unroll
        for (int nt = 0; nt < 8; ++nt) {
            const int p = nt >> 1, o = nt & 1;
            mma_bf16(acc[nt], ah[0], ah[1], ah[2], ah[3], bl[4*p+o], bl[4*p+2+o]);
        }
#pragma unroll
        for (int nt = 0; nt < 8; ++nt) {
            const int p = nt >> 1, o = nt & 1;
            mma_bf16(acc[nt], al[0], al[1], al[2], al[3], bh[4*p+o], bh[4*p+2+o]);
        }
    }
}

// ---------------------------------------------------------------------------
// Kernel 0a/0b: edge_index dtype detect + normalize.
// ---------------------------------------------------------------------------
__global__ void egnn_detect_kernel(const long long* __restrict__ ei, const int E)
{
    __shared__ int bad;
    if (threadIdx.x == 0) bad = 0;
    __syncthreads();
    const int cnt = E < 1024 ? E : 1024;
    for (int i = threadIdx.x; i < cnt; i += blockDim.x) {
        const long long v = ei[i];
        if (v < 0 || v > 0x7FFFFFFFLL) bad = 1;
    }
    __syncthreads();
    if (threadIdx.x == 0) d_e32flag = bad;
}

__global__ void egnn_cvt_kernel(const void* __restrict__ ei, const int E)
{
    const int i = blockIdx.x * blockDim.x + threadIdx.x;
    if (i >= 2 * E) return;
    int v;
    if (d_e32flag) v = ((const int*)ei)[i];
    else           v = (int)(((const long long*)ei)[i]);
    if (i < E) d_src[i] = v;
    else       d_dst[i - E] = v;
}

// ---------------------------------------------------------------------------
// Kernel 1: hsum = h + h_init; zero accumulators.
// ---------------------------------------------------------------------------
__global__ void egnn_init_kernel(const float* __restrict__ h,
                                 const float* __restrict__ hi, const int N)
{
    const int i = blockIdx.x * blockDim.x + threadIdx.x;
    const int n4 = N * 16;
    if (i < n4) {
        const float4 a = reinterpret_cast<const float4*>(h)[i];
        const float4 b = reinterpret_cast<const float4*>(hi)[i];
        float4 s;
        s.x = a.x + b.x; s.y = a.y + b.y; s.z = a.z + b.z; s.w = a.w + b.w;
        reinterpret_cast<float4*>(d_hsum)[i] = s;
        reinterpret_cast<float4*>(d_agg)[i] = make_float4(0.f, 0.f, 0.f, 0.f);
    }
    if (i < N) d_deg[i] = 0.0f;
    if (i < N * 2) d_posacc[i] = 0.0f;
}

// ---------------------------------------------------------------------------
// Kernel 2: persistent mma.sync edge kernel. 512 threads; 256-edge tiles.
// ---------------------------------------------------------------------------
__global__ void __launch_bounds__(NTHREADS, 1)
egnn_edge_kernel(const float* __restrict__ pos,
                 const float* __restrict__ Wm1, const float* __restrict__ bm1,
                 const float* __restrict__ Wm2, const float* __restrict__ bm2,
                 const float* __restrict__ Wp1, const float* __restrict__ bp1,
                 const float* __restrict__ Wp2, const float* __restrict__ bp2,
                 const int E, const int N)
{
    extern __shared__ char smem[];
    const uint32_t su = smem_to_u32(smem);
    const int tid = threadIdx.x;
    const int wid = tid >> 5;
    const int lane = tid & 31;

    // ---- stage weights as bf16 hi/lo B-tiles (B[n][k] = W[k][n], SW128) ----
    for (int idx = tid; idx < 4096; idx += NTHREADS) {
        const int n = idx >> 6, k = idx & 63;
        const int off = n * 128 + ((k * 2) ^ ((n & 7) << 4));
        stage_pair(smem + OFF_B1A_HI + off, smem + OFF_B1A_LO + off, Wm1[k * 64 + n]);
        stage_pair(smem + OFF_B1B_HI + off, smem + OFF_B1B_LO + off, Wm1[(64 + k) * 64 + n]);
        stage_pair(smem + OFF_B2_HI  + off, smem + OFF_B2_LO  + off, Wm2[k * 64 + n]);
        stage_pair(smem + OFF_BP1_HI + off, smem + OFF_BP1_LO + off, Wp1[k * 64 + n]);
    }
    if (tid < 64) {
        ((float*)(smem + OFF_B1 ))[tid] = bm1[tid];
        ((float*)(smem + OFF_B2 ))[tid] = bm2[tid];
        ((float*)(smem + OFF_BP1))[tid] = bp1[tid];
        ((float*)(smem + OFF_W1C))[tid] = Wm1[128 * 64 + tid];
        ((float*)(smem + OFF_WP2))[tid] = Wp2[tid];
    }
    if (tid == 0) ((float*)(smem + OFF_BP2))[0] = bp2[0];
    __syncthreads();

    int* sidx   = (int*)(smem + OFF_SIDX);   // [0..255]=dst, [256..511]=src
    float* sd2  = (float*)(smem + OFF_D2);
    float* srel = (float*)(smem + OFF_REL);
    const float* sb1  = (const float*)(smem + OFF_B1);
    const float* sb2  = (const float*)(smem + OFF_B2);
    const float* sbp1 = (const float*)(smem + OFF_BP1);
    const float* sw1c = (const float*)(smem + OFF_W1C);
    const float* swp2 = (const float*)(smem + OFF_WP2);

    const int rowbase = wid * 16;         // this warp's 16 edges within tile
    const int l4 = lane & 3;
    const int rgrp = lane >> 2;
    const int r0 = rowbase + rgrp;
    const int r1 = r0 + 8;

    const int nTiles = (E + TILE_E - 1) / TILE_E;

    for (int t = blockIdx.x; t < nTiles; t += gridDim.x) {
        const int eBase = t * TILE_E;
        const bool isDst = (tid < TILE_E);
        const int erow = isDst ? tid : (tid - TILE_E);

        __syncthreads();   // previous tile fully consumed before overwrite

        // ---- gather phase: indices + A planes + rel/d2 (single barrier) ----
        {
            const int e = eBase + erow;
            int node = -1;
            if (e < E) node = isDst ? d_dst[e] : d_src[e];
            if ((unsigned)node >= (unsigned)N) node = -1;
            sidx[tid] = node;

            char* hiT = smem + (isDst ? OFF_ADST_HI : OFF_ASRC_HI);
            char* loT = smem + (isDst ? OFF_ADST_LO : OFF_ASRC_LO);
            const float4* srcp =
                reinterpret_cast<const float4*>(d_hsum) + (size_t)(node < 0 ? 0 : node) * 16;
#pragma unroll
            for (int i = 0; i < 8; ++i) {
                float4 a = make_float4(0.f, 0.f, 0.f, 0.f), b = a;
                if (node >= 0) { a = srcp[2 * i]; b = srcp[2 * i + 1]; }
                uint4 hi, lo;
                cvt_hilo(a, b, hi, lo);
                const int off = erow * 128 + ((i * 16) ^ ((erow & 7) << 4));
                *reinterpret_cast<uint4*>(hiT + off) = hi;
                *reinterpret_cast<uint4*>(loT + off) = lo;
            }

            if (isDst) {   // rel/d2 via direct global index loads (no sidx dep)
                int sn = -1;
                if (e < E) sn = d_src[e];
                if ((unsigned)sn >= (unsigned)N) sn = -1;
                float rx = 0.f, ry = 0.f;
                if (node >= 0 && sn >= 0) {
                    const float2 pd = reinterpret_cast<const float2*>(pos)[node];
                    const float2 ps = reinterpret_cast<const float2*>(pos)[sn];
                    rx = pd.x - ps.x; ry = pd.y - ps.y;
                }
                srel[2 * erow] = rx; srel[2 * erow + 1] = ry;
                sd2[erow] = rx * rx + ry * ry;
            }
        }
        __syncthreads();   // publish sidx + A planes + rel/d2

        float acc[8][4];

        // ================= GEMM1: t1 = silu(m_in @ W1 + d2*w1c + b1) =========
#pragma unroll
        for (int nt = 0; nt < 8; ++nt)
#pragma unroll
            for (int j = 0; j < 4; ++j) acc[nt][j] = 0.f;

        gemm_term_pass(acc, su + OFF_ADST_HI, su + OFF_ADST_LO,
                       su + OFF_B1A_HI, su + OFF_B1A_LO, rowbase, lane);
        gemm_term_pass(acc, su + OFF_ASRC_HI, su + OFF_ASRC_LO,
                       su + OFF_B1B_HI, su + OFF_B1B_LO, rowbase, lane);
        __syncwarp();   // all warp lanes done reading A-dst rows (T aliases them)

        {   // epilogue 1: bias + d2 rank-1 + silu, restage hi/lo into T
            const float dd0 = sd2[r0], dd1 = sd2[r1];
            const int sw0 = (r0 & 7) << 4, sw1 = (r1 & 7) << 4;
#pragma unroll
            for (int nt = 0; nt < 8; ++nt) {
                const int cb = nt * 8 + 2 * l4;
                const float w0 = sw1c[cb], w1 = sw1c[cb + 1];
                const float bb0 = sb1[cb], bb1 = sb1[cb + 1];
                const float v0 = silu_f(acc[nt][0] + dd0 * w0 + bb0);
                const float v1 = silu_f(acc[nt][1] + dd0 * w1 + bb1);
                const float v2 = silu_f(acc[nt][2] + dd1 * w0 + bb0);
                const float v3 = silu_f(acc[nt][3] + dd1 * w1 + bb1);
                const int o0 = r0 * 128 + ((nt * 16) ^ sw0) + 4 * l4;
                const int o1 = r1 * 128 + ((nt * 16) ^ sw1) + 4 * l4;
                stage_pair2(smem + OFF_T_HI + o0, smem + OFF_T_LO + o0, v0, v1);
                stage_pair2(smem + OFF_T_HI + o1, smem + OFF_T_LO + o1, v2, v3);
            }
        }
        __syncwarp();

        // ================= GEMM2: m = silu(t1 @ W2 + b2) ======================
#pragma unroll
        for (int nt = 0; nt < 8; ++nt)
#pragma unroll
            for (int j = 0; j < 4; ++j) acc[nt][j] = 0.f;

        gemm_term_pass(acc, su + OFF_T_HI, su + OFF_T_LO,
                       su + OFF_B2_HI, su + OFF_B2_LO, rowbase, lane);
        __syncwarp();   // all T reads done before restage

        {   // epilogue 2: silu, scatter agg (red.v2), restage m into T
            const int dn0 = sidx[r0], dn1 = sidx[r1];
            float* agg0 = d_agg + (size_t)(dn0 < 0 ? 0 : dn0) * 64;
            float* agg1 = d_agg + (size_t)(dn1 < 0 ? 0 : dn1) * 64;
            const int sw0 = (r0 & 7) << 4, sw1 = (r1 & 7) << 4;
#pragma unroll
            for (int nt = 0; nt < 8; ++nt) {
                const int cb = nt * 8 + 2 * l4;
                const float bb0 = sb2[cb], bb1 = sb2[cb + 1];
                const float v0 = silu_f(acc[nt][0] + bb0);
                const float v1 = silu_f(acc[nt][1] + bb1);
                const float v2 = silu_f(acc[nt][2] + bb0);
                const float v3 = silu_f(acc[nt][3] + bb1);
                if (dn0 >= 0) red_add_v2(agg0 + cb, v0, v1);
                if (dn1 >= 0) red_add_v2(agg1 + cb, v2, v3);
                const int o0 = r0 * 128 + ((nt * 16) ^ sw0) + 4 * l4;
                const int o1 = r1 * 128 + ((nt * 16) ^ sw1) + 4 * l4;
                stage_pair2(smem + OFF_T_HI + o0, smem + OFF_T_LO + o0, v0, v1);
                stage_pair2(smem + OFF_T_HI + o1, smem + OFF_T_LO + o1, v2, v3);
            }
        }
        __syncwarp();

        // ============ GEMM3: w = silu(m @ Wp1 + bp1) . Wp2 + bp2 ==============
#pragma unroll
        for (int nt = 0; nt < 8; ++nt)
#pragma unroll
            for (int j = 0; j < 4; ++j) acc[nt][j] = 0.f;

        gemm_term_pass(acc, su + OFF_T_HI, su + OFF_T_LO,
                       su + OFF_BP1_HI, su + OFF_BP1_LO, rowbase, lane);

        {   // epilogue 3: per-row dot with Wp2, 4-lane reduce, pos scatter
            float p0 = 0.f, p1 = 0.f;
#pragma unroll
            for (int nt = 0; nt < 8; ++nt) {
                const int cb = nt * 8 + 2 * l4;
                const float bb0 = sbp1[cb], bb1 = sbp1[cb + 1];
                const float w0 = swp2[cb], w1 = swp2[cb + 1];
                p0 += silu_f(acc[nt][0] + bb0) * w0 + silu_f(acc[nt][1] + bb1) * w1;
                p1 += silu_f(acc[nt][2] + bb0) * w0 + silu_f(acc[nt][3] + bb1) * w1;
            }
            p0 += __shfl_xor_sync(0xFFFFFFFFu, p0, 1);
            p0 += __shfl_xor_sync(0xFFFFFFFFu, p0, 2);
            p1 += __shfl_xor_sync(0xFFFFFFFFu, p1, 1);
            p1 += __shfl_xor_sync(0xFFFFFFFFu, p1, 2);
            if (l4 == 0) {
                const float bp2v = ((const float*)(smem + OFF_BP2))[0];
                const int dn0 = sidx[r0], dn1 = sidx[r1];
                if (dn0 >= 0) {
                    const float w = p0 + bp2v;
                    red_add_v2(&d_posacc[dn0 * 2], srel[2 * r0] * w, srel[2 * r0 + 1] * w);
                    atomicAdd(&d_deg[dn0], 1.0f);
                }
                if (dn1 >= 0) {
                    const float w = p1 + bp2v;
                    red_add_v2(&d_posacc[dn1 * 2], srel[2 * r1] * w, srel[2 * r1 + 1] * w);
                    atomicAdd(&d_deg[dn1], 1.0f);
                }
            }
        }
    }
}

// ---------------------------------------------------------------------------
// Kernel 3: node update (phi_h) + skip connections + pos update. Warp/node.
// ---------------------------------------------------------------------------
__global__ void __launch_bounds__(128, 4)
egnn_node_kernel(const float* __restrict__ pos,
                 const float* __restrict__ Wh1, const float* __restrict__ bh1,
                 const float* __restrict__ Wh2, const float* __restrict__ bh2,
                 float* __restrict__ out, const int N)
{
    extern __shared__ float sm[];
    const int tid = threadIdx.x;

    for (int i = tid; i < 8192; i += 128) sm[NS_WH1 + i] = Wh1[i];
    for (int i = tid; i < 4096; i += 128) sm[NS_WH2 + i] = Wh2[i];
    if (tid < 64) {
        sm[NS_BH1 + tid] = bh1[tid];
        sm[NS_BH2 + tid] = bh2[tid];
    }
    __syncthreads();

    const int w = tid >> 5, lane = tid & 31;
    float* sx = sm + NS_X + w * 128;
    float* sy = sm + NS_Y + w * 64;
    const float bb10 = sm[NS_BH1 + 2 * lane], bb11 = sm[NS_BH1 + 2 * lane + 1];
    const float bb20 = sm[NS_BH2 + 2 * lane], bb21 = sm[NS_BH2 + 2 * lane + 1];

    const int gw = blockIdx.x * 4 + w;
    const int nw = gridDim.x * 4;
    float* out_pos = out + (long long)N * 64;

    for (int n = gw; n < N; n += nw) {
        sx[lane]      = d_hsum[n * 64 + lane];
        sx[32 + lane] = d_hsum[n * 64 + 32 + lane];
        sx[64 + lane] = d_agg[n * 64 + lane];
        sx[96 + lane] = d_agg[n * 64 + 32 + lane];
        __syncwarp();

        ull acc = 0ULL;
#pragma unroll 4
        for (int i = 0; i < 128; ++i) {
            const float a = sx[i];
            const ull b = reinterpret_cast<const ull*>(sm + NS_WH1 + i * 64)[lane];
            acc = fma2(pk2(a, a), b, acc);
        }
        float y0, y1;
        upk2(acc, y0, y1);
        y0 = silu_f(y0 + bb10);
        y1 = silu_f(y1 + bb11);
        *reinterpret_cast<float2*>(sy + 2 * lane) = make_float2(y0, y1);
        __syncwarp();

        acc = 0ULL;
#pragma unroll 4
        for (int i = 0; i < 64; ++i) {
            const float a = sy[i];
            const ull b = reinterpret_cast<const ull*>(sm + NS_WH2 + i * 64)[lane];
            acc = fma2(pk2(a, a), b, acc);
        }
        float o0, o1;
        upk2(acc, o0, o1);
        o0 += bb20 + sx[2 * lane];
        o1 += bb21 + sx[2 * lane + 1];
        *reinterpret_cast<float2*>(out + (long long)n * 64 + 2 * lane) = make_float2(o0, o1);

        if (lane < 2) {
            const float dg = fmaxf(d_deg[n], 1.0f);
            out_pos[n * 2 + lane] = pos[n * 2 + lane] + d_posacc[n * 2 + lane] / dg;
        }
        __syncwarp();
    }
}

// ---------------------------------------------------------------------------
extern "C" void kernel_launch(void* const* d_in, const int* in_sizes, int n_in,
                              void* d_out, int out_size)
{
    const float* h      = (const float*)d_in[0];
    const float* pos    = (const float*)d_in[1];
    const float* h_init = (const float*)d_in[2];
    const float* Wm1    = (const float*)d_in[3];
    const float* bm1    = (const float*)d_in[4];
    const float* Wm2    = (const float*)d_in[5];
    const float* bm2    = (const float*)d_in[6];
    const float* Wp1    = (const float*)d_in[7];
    const float* bp1    = (const float*)d_in[8];
    const float* Wp2    = (const float*)d_in[9];
    const float* bp2    = (const float*)d_in[10];
    const float* Wh1    = (const float*)d_in[11];
    const float* bh1    = (const float*)d_in[12];
    const float* Wh2    = (const float*)d_in[13];
    const float* bh2    = (const float*)d_in[14];
    const void*  ei     = d_in[15];

    const int N = in_sizes[0] / 64;
    const int E = in_sizes[15] / 2;
    float* out = (float*)d_out;

    cudaFuncSetAttribute(egnn_edge_kernel,
                         cudaFuncAttributeMaxDynamicSharedMemorySize, EDGE_SMEM_BYTES);
    cudaFuncSetAttribute(egnn_node_kernel,
                         cudaFuncAttributeMaxDynamicSharedMemorySize, NODE_SMEM_BYTES);

    egnn_detect_kernel<<<1, 256>>>((const long long*)ei, E);
    egnn_cvt_kernel<<<(2 * E + 255) / 256, 256>>>(ei, E);
    egnn_init_kernel<<<(N * 16 + 255) / 256, 256>>>(h, h_init, N);

    const int nTiles = (E + TILE_E - 1) / TILE_E;
    int eblocks = nTiles < 148 ? nTiles : 148;
    egnn_edge_kernel<<<eblocks, NTHREADS, EDGE_SMEM_BYTES>>>(
        pos, Wm1, bm1, Wm2, bm2, Wp1, bp1, Wp2, bp2, E, N);

    egnn_node_kernel<<<592, 128, NODE_SMEM_BYTES>>>(pos, Wh1, bh1, Wh2, bh2, out, N);
}

// round 11
// speedup vs baseline: 2.8308x; 1.2192x over previous
#include <cuda_runtime.h>
#include <cuda_bf16.h>
#include <stdint.h>

// ---------------------------------------------------------------------------
// EGNN / SpatialNCA step.  N=50000 nodes, D=64, E=800000 edges, P=2.
//
// R11: latency-path surgery on the mma.sync edge kernel.
//  - Coalesced gather: 16 lanes per 256B row (4 wavefronts/instr vs 32).
//  - GEMM2/GEMM3 take A directly from registers: the m16n8 accumulator
//    fragment layout equals the m16n8k16 A-fragment layout, so epilogues
//    split hi/lo in regs (no T buffer, no restage STS, no A-LDSM, no
//    intra-tile syncwarps). 2 block barriers per tile, nothing else.
// ---------------------------------------------------------------------------

typedef unsigned long long ull;

#define MAXN 50000
#define MAXD 64
#define MAXE 800000

// scratch (device globals: allocation-free rule)
__device__ __align__(16) float d_hsum[MAXN * MAXD];
__device__ __align__(16) float d_agg[MAXN * MAXD];
__device__ __align__(16) float d_posacc[MAXN * 2];
__device__ float d_deg[MAXN];
__device__ int   d_src[MAXE];
__device__ int   d_dst[MAXE];
__device__ int   d_e32flag;   // 1 if edge_index buffer is int32, 0 if int64

// ---- small helpers ----------------------------------------------------------
__device__ __forceinline__ uint32_t smem_to_u32(const void* p) {
    uint32_t a;
    asm("{ .reg .u64 t; cvta.to.shared.u64 t, %1; cvt.u32.u64 %0, t; }"
        : "=r"(a) : "l"(p));
    return a;
}
__device__ __forceinline__ float silu_f(float x) {
    return x / (1.0f + __expf(-x));
}
__device__ __forceinline__ void red_add_v2(float* p, float x, float y) {
    asm volatile("red.global.add.v2.f32 [%0], {%1, %2};"
                 :: "l"(p), "f"(x), "f"(y) : "memory");
}
__device__ __forceinline__ ull pk2(float lo, float hi) {
    ull r; asm("mov.b64 %0, {%1,%2};" : "=l"(r) : "f"(lo), "f"(hi)); return r;
}
__device__ __forceinline__ void upk2(ull v, float& lo, float& hi) {
    asm("mov.b64 {%0,%1}, %2;" : "=f"(lo), "=f"(hi) : "l"(v));
}
__device__ __forceinline__ ull fma2(ull a, ull b, ull c) {
    ull d; asm("fma.rn.f32x2 %0, %1, %2, %3;" : "=l"(d) : "l"(a), "l"(b), "l"(c));
    return d;
}

// ---- mma / ldmatrix primitives (sm_80-compatible, run on sm_100 HMMA) -------
__device__ __forceinline__ void ldsm_x4(uint32_t& r0, uint32_t& r1,
                                        uint32_t& r2, uint32_t& r3, uint32_t addr) {
    asm volatile("ldmatrix.sync.aligned.m8n8.x4.shared.b16 {%0,%1,%2,%3}, [%4];"
                 : "=r"(r0), "=r"(r1), "=r"(r2), "=r"(r3) : "r"(addr));
}
__device__ __forceinline__ void mma_bf16(float* c,
                                         uint32_t a0, uint32_t a1, uint32_t a2, uint32_t a3,
                                         uint32_t b0, uint32_t b1) {
    asm volatile("mma.sync.aligned.m16n8k16.row.col.f32.bf16.bf16.f32 "
                 "{%0,%1,%2,%3}, {%4,%5,%6,%7}, {%8,%9}, {%0,%1,%2,%3};"
                 : "+f"(c[0]), "+f"(c[1]), "+f"(c[2]), "+f"(c[3])
                 : "r"(a0), "r"(a1), "r"(a2), "r"(a3), "r"(b0), "r"(b1));
}

// lane-specific ldmatrix.x4 address into a [rows x 64 bf16] SW128 plane
// (row stride 128B, 16B-granule XOR swizzle ((row&7)<<4)).
__device__ __forceinline__ uint32_t lds_addr(uint32_t base, int rowbase, int kc, int lane) {
    const int quad = lane >> 3, r8 = lane & 7;
    const int row = rowbase + r8 + (quad & 1) * 8;
    const int kb = kc * 32 + (quad >> 1) * 16;
    return base + row * 128 + (kb ^ ((row & 7) << 4));
}

// ---- bf16 hi/lo split helpers ------------------------------------------------
__device__ __forceinline__ uint32_t pack_bf2(float x, float y) {
    __nv_bfloat162 h = __floats2bfloat162_rn(x, y);
    return *reinterpret_cast<uint32_t*>(&h);
}
__device__ __forceinline__ float2 unpack_bf2(uint32_t u) {
    __nv_bfloat162 h = *reinterpret_cast<__nv_bfloat162*>(&u);
    return __bfloat1622float2(h);
}
__device__ __forceinline__ void stage_pair(char* hip, char* lop, float v) {
    __nv_bfloat16 h = __float2bfloat16_rn(v);
    float r = v - __bfloat162float(h);
    __nv_bfloat16 l = __float2bfloat16_rn(r);
    *reinterpret_cast<__nv_bfloat16*>(hip) = h;
    *reinterpret_cast<__nv_bfloat16*>(lop) = l;
}
// split two floats into packed bf16 hi + lo
__device__ __forceinline__ void split2(float x, float y, uint32_t& hi, uint32_t& lo) {
    hi = pack_bf2(x, y);
    const float2 f = unpack_bf2(hi);
    lo = pack_bf2(x - f.x, y - f.y);
}

// ---- edge kernel config ------------------------------------------------------
constexpr int TILE_E   = 256;               // edges per tile (16 warps x 16)
constexpr int NTHREADS = 512;

// smem byte offsets
constexpr int OFF_SIDX = 0;                 // 256 ints (dst nodes)
constexpr int OFF_D2   = 1024;              // 256 f32
constexpr int OFF_REL  = 2048;              // 512 f32
constexpr int OFF_B1   = 4096;              // 64 f32 each below
constexpr int OFF_B2   = 4352;
constexpr int OFF_BP1  = 4608;
constexpr int OFF_W1C  = 4864;              // W_msg1 row 128 (d2 rank-1)
constexpr int OFF_WP2  = 5120;
constexpr int OFF_BP2  = 5376;
// weight B-tiles [n=64][k=64] bf16 SW128 (8KB each)
constexpr int OFF_B1A_HI = 8192;
constexpr int OFF_B1A_LO = 16384;
constexpr int OFF_B1B_HI = 24576;
constexpr int OFF_B1B_LO = 32768;
constexpr int OFF_B2_HI  = 40960;
constexpr int OFF_B2_LO  = 49152;
constexpr int OFF_BP1_HI = 57344;
constexpr int OFF_BP1_LO = 65536;
// A-tiles [256 x 64] bf16 SW128 (32KB each)
constexpr int OFF_ADST_HI = 73728;
constexpr int OFF_ADST_LO = 106496;
constexpr int OFF_ASRC_HI = 139264;
constexpr int OFF_ASRC_LO = 172032;
constexpr int EDGE_SMEM_BYTES = 204800;     // 200 KB

// ---- node kernel smem layout (floats) ----------------------------------------
constexpr int NS_WH1 = 0;
constexpr int NS_WH2 = 8192;
constexpr int NS_BH1 = 12288;
constexpr int NS_BH2 = 12352;
constexpr int NS_X   = 12416;
constexpr int NS_Y   = 12928;
constexpr int NODE_SMEM_BYTES = (NS_Y + 256) * 4;

// ---------------------------------------------------------------------------
// 3-term GEMM over K=64, A from smem plane (GEMM1 halves).
// B-frags chunked per 8-col tile to bound register live range.
// ---------------------------------------------------------------------------
__device__ __forceinline__ void gemm_smemA(
    float acc[8][4],
    uint32_t aHi, uint32_t aLo, uint32_t bHi, uint32_t bLo,
    int rowbase, int lane)
{
#pragma unroll
    for (int kc = 0; kc < 4; ++kc) {
        uint32_t ah[4], al[4];
        ldsm_x4(ah[0], ah[1], ah[2], ah[3], lds_addr(aHi, rowbase, kc, lane));
        ldsm_x4(al[0], al[1], al[2], al[3], lds_addr(aLo, rowbase, kc, lane));
#pragma unroll
        for (int p = 0; p < 4; ++p) {
            uint32_t bh[4], bl[4];
            ldsm_x4(bh[0], bh[1], bh[2], bh[3], lds_addr(bHi, 16 * p, kc, lane));
            ldsm_x4(bl[0], bl[1], bl[2], bl[3], lds_addr(bLo, 16 * p, kc, lane));
#pragma unroll
            for (int o = 0; o < 2; ++o) {
                const int nt = 2 * p + o;
                mma_bf16(acc[nt], ah[0], ah[1], ah[2], ah[3], bh[o], bh[2 + o]);
                mma_bf16(acc[nt], ah[0], ah[1], ah[2], ah[3], bl[o], bl[2 + o]);
                mma_bf16(acc[nt], al[0], al[1], al[2], al[3], bh[o], bh[2 + o]);
            }
        }
    }
}

// 3-term GEMM over K=64, A from registers (af = 16 hi + 16 lo frags).
__device__ __forceinline__ void gemm_regA(
    float acc[8][4],
    const uint32_t afh[16], const uint32_t afl[16],
    uint32_t bHi, uint32_t bLo, int lane)
{
#pragma unroll
    for (int kc = 0; kc < 4; ++kc) {
        const uint32_t* ah = afh + 4 * kc;
        const uint32_t* al = afl + 4 * kc;
#pragma unroll
        for (int p = 0; p < 4; ++p) {
            uint32_t bh[4], bl[4];
            ldsm_x4(bh[0], bh[1], bh[2], bh[3], lds_addr(bHi, 16 * p, kc, lane));
            ldsm_x4(bl[0], bl[1], bl[2], bl[3], lds_addr(bLo, 16 * p, kc, lane));
#pragma unroll
            for (int o = 0; o < 2; ++o) {
                const int nt = 2 * p + o;
                mma_bf16(acc[nt], ah[0], ah[1], ah[2], ah[3], bh[o], bh[2 + o]);
                mma_bf16(acc[nt], ah[0], ah[1], ah[2], ah[3], bl[o], bl[2 + o]);
                mma_bf16(acc[nt], al[0], al[1], al[2], al[3], bh[o], bh[2 + o]);
            }
        }
    }
}

// Convert activation values (accumulator layout) into next-GEMM A-fragments.
// Acc layout: v[nt][0,1] = row r0 cols nt*8+2l4,+1 ; v[nt][2,3] = row r1.
// A-frag kk:  a0=(r0, 16kk+2l4..) = v[2kk][0,1] ; a1=(r1,..) = v[2kk][2,3] ;
//             a2=(r0, +8)         = v[2kk+1][0,1]; a3=(r1,+8) = v[2kk+1][2,3].
__device__ __forceinline__ void make_afrag(
    const float v[8][4], uint32_t afh[16], uint32_t afl[16])
{
#pragma unroll
    for (int kk = 0; kk < 4; ++kk) {
        split2(v[2*kk][0],   v[2*kk][1],   afh[4*kk + 0], afl[4*kk + 0]);
        split2(v[2*kk][2],   v[2*kk][3],   afh[4*kk + 1], afl[4*kk + 1]);
        split2(v[2*kk+1][0], v[2*kk+1][1], afh[4*kk + 2], afl[4*kk + 2]);
        split2(v[2*kk+1][2], v[2*kk+1][3], afh[4*kk + 3], afl[4*kk + 3]);
    }
}

// ---------------------------------------------------------------------------
// Kernel 0a/0b: edge_index dtype detect + normalize.
// ---------------------------------------------------------------------------
__global__ void egnn_detect_kernel(const long long* __restrict__ ei, const int E)
{
    __shared__ int bad;
    if (threadIdx.x == 0) bad = 0;
    __syncthreads();
    const int cnt = E < 1024 ? E : 1024;
    for (int i = threadIdx.x; i < cnt; i += blockDim.x) {
        const long long v = ei[i];
        if (v < 0 || v > 0x7FFFFFFFLL) bad = 1;
    }
    __syncthreads();
    if (threadIdx.x == 0) d_e32flag = bad;
}

__global__ void egnn_cvt_kernel(const void* __restrict__ ei, const int E)
{
    const int i = blockIdx.x * blockDim.x + threadIdx.x;
    if (i >= 2 * E) return;
    int v;
    if (d_e32flag) v = ((const int*)ei)[i];
    else           v = (int)(((const long long*)ei)[i]);
    if (i < E) d_src[i] = v;
    else       d_dst[i - E] = v;
}

// ---------------------------------------------------------------------------
// Kernel 1: hsum = h + h_init; zero accumulators.
// ---------------------------------------------------------------------------
__global__ void egnn_init_kernel(const float* __restrict__ h,
                                 const float* __restrict__ hi, const int N)
{
    const int i = blockIdx.x * blockDim.x + threadIdx.x;
    const int n4 = N * 16;
    if (i < n4) {
        const float4 a = reinterpret_cast<const float4*>(h)[i];
        const float4 b = reinterpret_cast<const float4*>(hi)[i];
        float4 s;
        s.x = a.x + b.x; s.y = a.y + b.y; s.z = a.z + b.z; s.w = a.w + b.w;
        reinterpret_cast<float4*>(d_hsum)[i] = s;
        reinterpret_cast<float4*>(d_agg)[i] = make_float4(0.f, 0.f, 0.f, 0.f);
    }
    if (i < N) d_deg[i] = 0.0f;
    if (i < N * 2) d_posacc[i] = 0.0f;
}

// ---------------------------------------------------------------------------
// Kernel 2: persistent mma.sync edge kernel. 512 threads; 256-edge tiles.
// ---------------------------------------------------------------------------
__global__ void __launch_bounds__(NTHREADS, 1)
egnn_edge_kernel(const float* __restrict__ pos,
                 const float* __restrict__ Wm1, const float* __restrict__ bm1,
                 const float* __restrict__ Wm2, const float* __restrict__ bm2,
                 const float* __restrict__ Wp1, const float* __restrict__ bp1,
                 const float* __restrict__ Wp2, const float* __restrict__ bp2,
                 const int E, const int N)
{
    extern __shared__ char smem[];
    const uint32_t su = smem_to_u32(smem);
    const int tid = threadIdx.x;
    const int wid = tid >> 5;
    const int lane = tid & 31;

    // ---- stage weights as bf16 hi/lo B-tiles (B[n][k] = W[k][n], SW128) ----
    for (int idx = tid; idx < 4096; idx += NTHREADS) {
        const int n = idx >> 6, k = idx & 63;
        const int off = n * 128 + ((k * 2) ^ ((n & 7) << 4));
        stage_pair(smem + OFF_B1A_HI + off, smem + OFF_B1A_LO + off, Wm1[k * 64 + n]);
        stage_pair(smem + OFF_B1B_HI + off, smem + OFF_B1B_LO + off, Wm1[(64 + k) * 64 + n]);
        stage_pair(smem + OFF_B2_HI  + off, smem + OFF_B2_LO  + off, Wm2[k * 64 + n]);
        stage_pair(smem + OFF_BP1_HI + off, smem + OFF_BP1_LO + off, Wp1[k * 64 + n]);
    }
    if (tid < 64) {
        ((float*)(smem + OFF_B1 ))[tid] = bm1[tid];
        ((float*)(smem + OFF_B2 ))[tid] = bm2[tid];
        ((float*)(smem + OFF_BP1))[tid] = bp1[tid];
        ((float*)(smem + OFF_W1C))[tid] = Wm1[128 * 64 + tid];
        ((float*)(smem + OFF_WP2))[tid] = Wp2[tid];
    }
    if (tid == 0) ((float*)(smem + OFF_BP2))[0] = bp2[0];
    __syncthreads();

    int* sidx   = (int*)(smem + OFF_SIDX);   // dst nodes [0..255]
    float* sd2  = (float*)(smem + OFF_D2);
    float* srel = (float*)(smem + OFF_REL);
    const float* sb1  = (const float*)(smem + OFF_B1);
    const float* sb2  = (const float*)(smem + OFF_B2);
    const float* sbp1 = (const float*)(smem + OFF_BP1);
    const float* sw1c = (const float*)(smem + OFF_W1C);
    const float* swp2 = (const float*)(smem + OFF_WP2);

    const int rowbase = wid * 16;         // this warp's 16 edges within tile
    const int l4 = lane & 3;
    const int rgrp = lane >> 2;
    const int r0 = rowbase + rgrp;
    const int r1 = r0 + 8;

    const int nTiles = (E + TILE_E - 1) / TILE_E;

    for (int t = blockIdx.x; t < nTiles; t += gridDim.x) {
        const int eBase = t * TILE_E;

        // ---- gather phase (coalesced: 16 lanes per 256B row) ----
        if (tid < TILE_E) {      // indices + rel/d2 (one edge per thread)
            const int e = eBase + tid;
            int dn = -1, sn = -1;
            if (e < E) { dn = d_dst[e]; sn = d_src[e]; }
            if ((unsigned)dn >= (unsigned)N) dn = -1;
            if ((unsigned)sn >= (unsigned)N) sn = -1;
            sidx[tid] = dn;
            float rx = 0.f, ry = 0.f;
            if (dn >= 0 && sn >= 0) {
                const float2 pd = reinterpret_cast<const float2*>(pos)[dn];
                const float2 ps = reinterpret_cast<const float2*>(pos)[sn];
                rx = pd.x - ps.x; ry = pd.y - ps.y;
            }
            srel[2 * tid] = rx; srel[2 * tid + 1] = ry;
            sd2[tid] = rx * rx + ry * ry;
        }
#pragma unroll
        for (int i = 0; i < 16; ++i) {
            const int gidx = tid + i * NTHREADS;      // 0..8191
            const int row  = gidx >> 4;               // 0..511
            const int seg  = gidx & 15;               // 16B fp32 segment
            const bool dstp = (row < TILE_E);
            const int er = dstp ? row : row - TILE_E;
            const int e = eBase + er;
            int node = -1;
            if (e < E) node = dstp ? d_dst[e] : d_src[e];
            if ((unsigned)node >= (unsigned)N) node = -1;
            float4 a = make_float4(0.f, 0.f, 0.f, 0.f);
            if (node >= 0)
                a = reinterpret_cast<const float4*>(d_hsum)[node * 16 + seg];
            uint32_t h0, l0, h1, l1;
            split2(a.x, a.y, h0, l0);
            split2(a.z, a.w, h1, l1);
            const int boff = er * 128 + ((((seg >> 1) << 4)) ^ ((er & 7) << 4)) + (seg & 1) * 8;
            char* hiT = smem + (dstp ? OFF_ADST_HI : OFF_ASRC_HI);
            char* loT = smem + (dstp ? OFF_ADST_LO : OFF_ASRC_LO);
            *reinterpret_cast<uint2*>(hiT + boff) = make_uint2(h0, h1);
            *reinterpret_cast<uint2*>(loT + boff) = make_uint2(l0, l1);
        }
        __syncthreads();   // planes + sidx + rel/d2 published

        float acc[8][4];
        uint32_t afh[16], afl[16];

        // ===== GEMM1: t1 = silu(m_in @ W1 + d2*w1c + b1) (A from smem) ======
#pragma unroll
        for (int nt = 0; nt < 8; ++nt)
#pragma unroll
            for (int j = 0; j < 4; ++j) acc[nt][j] = 0.f;

        gemm_smemA(acc, su + OFF_ADST_HI, su + OFF_ADST_LO,
                   su + OFF_B1A_HI, su + OFF_B1A_LO, rowbase, lane);
        gemm_smemA(acc, su + OFF_ASRC_HI, su + OFF_ASRC_LO,
                   su + OFF_B1B_HI, su + OFF_B1B_LO, rowbase, lane);

        {   // epilogue 1: bias + d2 rank-1 + silu (in place), then A-frags
            const float dd0 = sd2[r0], dd1 = sd2[r1];
#pragma unroll
            for (int nt = 0; nt < 8; ++nt) {
                const int cb = nt * 8 + 2 * l4;
                const float w0 = sw1c[cb], w1 = sw1c[cb + 1];
                const float bb0 = sb1[cb], bb1 = sb1[cb + 1];
                acc[nt][0] = silu_f(acc[nt][0] + dd0 * w0 + bb0);
                acc[nt][1] = silu_f(acc[nt][1] + dd0 * w1 + bb1);
                acc[nt][2] = silu_f(acc[nt][2] + dd1 * w0 + bb0);
                acc[nt][3] = silu_f(acc[nt][3] + dd1 * w1 + bb1);
            }
            make_afrag(acc, afh, afl);
        }

        // ===== GEMM2: m = silu(t1 @ W2 + b2) (A from regs) ===================
#pragma unroll
        for (int nt = 0; nt < 8; ++nt)
#pragma unroll
            for (int j = 0; j < 4; ++j) acc[nt][j] = 0.f;

        gemm_regA(acc, afh, afl, su + OFF_B2_HI, su + OFF_B2_LO, lane);

        {   // epilogue 2: silu (in place), scatter agg, then A-frags
            const int dn0 = sidx[r0], dn1 = sidx[r1];
            float* agg0 = d_agg + (size_t)(dn0 < 0 ? 0 : dn0) * 64;
            float* agg1 = d_agg + (size_t)(dn1 < 0 ? 0 : dn1) * 64;
#pragma unroll
            for (int nt = 0; nt < 8; ++nt) {
                const int cb = nt * 8 + 2 * l4;
                const float bb0 = sb2[cb], bb1 = sb2[cb + 1];
                acc[nt][0] = silu_f(acc[nt][0] + bb0);
                acc[nt][1] = silu_f(acc[nt][1] + bb1);
                acc[nt][2] = silu_f(acc[nt][2] + bb0);
                acc[nt][3] = silu_f(acc[nt][3] + bb1);
                if (dn0 >= 0) red_add_v2(agg0 + cb, acc[nt][0], acc[nt][1]);
                if (dn1 >= 0) red_add_v2(agg1 + cb, acc[nt][2], acc[nt][3]);
            }
            make_afrag(acc, afh, afl);
        }

        // ===== GEMM3: w = silu(m @ Wp1 + bp1) . Wp2 + bp2 (A from regs) ======
#pragma unroll
        for (int nt = 0; nt < 8; ++nt)
#pragma unroll
            for (int j = 0; j < 4; ++j) acc[nt][j] = 0.f;

        gemm_regA(acc, afh, afl, su + OFF_BP1_HI, su + OFF_BP1_LO, lane);

        {   // epilogue 3: per-row dot with Wp2, 4-lane reduce, pos scatter
            float p0 = 0.f, p1 = 0.f;
#pragma unroll
            for (int nt = 0; nt < 8; ++nt) {
                const int cb = nt * 8 + 2 * l4;
                const float bb0 = sbp1[cb], bb1 = sbp1[cb + 1];
                const float w0 = swp2[cb], w1 = swp2[cb + 1];
                p0 += silu_f(acc[nt][0] + bb0) * w0 + silu_f(acc[nt][1] + bb1) * w1;
                p1 += silu_f(acc[nt][2] + bb0) * w0 + silu_f(acc[nt][3] + bb1) * w1;
            }
            p0 += __shfl_xor_sync(0xFFFFFFFFu, p0, 1);
            p0 += __shfl_xor_sync(0xFFFFFFFFu, p0, 2);
            p1 += __shfl_xor_sync(0xFFFFFFFFu, p1, 1);
            p1 += __shfl_xor_sync(0xFFFFFFFFu, p1, 2);
            if (l4 == 0) {
                const float bp2v = ((const float*)(smem + OFF_BP2))[0];
                const int dn0 = sidx[r0], dn1 = sidx[r1];
                if (dn0 >= 0) {
                    const float w = p0 + bp2v;
                    red_add_v2(&d_posacc[dn0 * 2], srel[2 * r0] * w, srel[2 * r0 + 1] * w);
                    atomicAdd(&d_deg[dn0], 1.0f);
                }
                if (dn1 >= 0) {
                    const float w = p1 + bp2v;
                    red_add_v2(&d_posacc[dn1 * 2], srel[2 * r1] * w, srel[2 * r1 + 1] * w);
                    atomicAdd(&d_deg[dn1], 1.0f);
                }
            }
        }
        __syncthreads();   // all warps done with planes/sidx/rel before next tile
    }
}

// ---------------------------------------------------------------------------
// Kernel 3: node update (phi_h) + skip connections + pos update. Warp/node.
// ---------------------------------------------------------------------------
__global__ void __launch_bounds__(128, 4)
egnn_node_kernel(const float* __restrict__ pos,
                 const float* __restrict__ Wh1, const float* __restrict__ bh1,
                 const float* __restrict__ Wh2, const float* __restrict__ bh2,
                 float* __restrict__ out, const int N)
{
    extern __shared__ float sm[];
    const int tid = threadIdx.x;

    for (int i = tid; i < 8192; i += 128) sm[NS_WH1 + i] = Wh1[i];
    for (int i = tid; i < 4096; i += 128) sm[NS_WH2 + i] = Wh2[i];
    if (tid < 64) {
        sm[NS_BH1 + tid] = bh1[tid];
        sm[NS_BH2 + tid] = bh2[tid];
    }
    __syncthreads();

    const int w = tid >> 5, lane = tid & 31;
    float* sx = sm + NS_X + w * 128;
    float* sy = sm + NS_Y + w * 64;
    const float bb10 = sm[NS_BH1 + 2 * lane], bb11 = sm[NS_BH1 + 2 * lane + 1];
    const float bb20 = sm[NS_BH2 + 2 * lane], bb21 = sm[NS_BH2 + 2 * lane + 1];

    const int gw = blockIdx.x * 4 + w;
    const int nw = gridDim.x * 4;
    float* out_pos = out + (long long)N * 64;

    for (int n = gw; n < N; n += nw) {
        sx[lane]      = d_hsum[n * 64 + lane];
        sx[32 + lane] = d_hsum[n * 64 + 32 + lane];
        sx[64 + lane] = d_agg[n * 64 + lane];
        sx[96 + lane] = d_agg[n * 64 + 32 + lane];
        __syncwarp();

        ull acc = 0ULL;
#pragma unroll 4
        for (int i = 0; i < 128; ++i) {
            const float a = sx[i];
            const ull b = reinterpret_cast<const ull*>(sm + NS_WH1 + i * 64)[lane];
            acc = fma2(pk2(a, a), b, acc);
        }
        float y0, y1;
        upk2(acc, y0, y1);
        y0 = silu_f(y0 + bb10);
        y1 = silu_f(y1 + bb11);
        *reinterpret_cast<float2*>(sy + 2 * lane) = make_float2(y0, y1);
        __syncwarp();

        acc = 0ULL;
#pragma unroll 4
        for (int i = 0; i < 64; ++i) {
            const float a = sy[i];
            const ull b = reinterpret_cast<const ull*>(sm + NS_WH2 + i * 64)[lane];
            acc = fma2(pk2(a, a), b, acc);
        }
        float o0, o1;
        upk2(acc, o0, o1);
        o0 += bb20 + sx[2 * lane];
        o1 += bb21 + sx[2 * lane + 1];
        *reinterpret_cast<float2*>(out + (long long)n * 64 + 2 * lane) = make_float2(o0, o1);

        if (lane < 2) {
            const float dg = fmaxf(d_deg[n], 1.0f);
            out_pos[n * 2 + lane] = pos[n * 2 + lane] + d_posacc[n * 2 + lane] / dg;
        }
        __syncwarp();
    }
}

// ---------------------------------------------------------------------------
extern "C" void kernel_launch(void* const* d_in, const int* in_sizes, int n_in,
                              void* d_out, int out_size)
{
    const float* h      = (const float*)d_in[0];
    const float* pos    = (const float*)d_in[1];
    const float* h_init = (const float*)d_in[2];
    const float* Wm1    = (const float*)d_in[3];
    const float* bm1    = (const float*)d_in[4];
    const float* Wm2    = (const float*)d_in[5];
    const float* bm2    = (const float*)d_in[6];
    const float* Wp1    = (const float*)d_in[7];
    const float* bp1    = (const float*)d_in[8];
    const float* Wp2    = (const float*)d_in[9];
    const float* bp2    = (const float*)d_in[10];
    const float* Wh1    = (const float*)d_in[11];
    const float* bh1    = (const float*)d_in[12];
    const float* Wh2    = (const float*)d_in[13];
    const float* bh2    = (const float*)d_in[14];
    const void*  ei     = d_in[15];

    const int N = in_sizes[0] / 64;
    const int E = in_sizes[15] / 2;
    float* out = (float*)d_out;

    cudaFuncSetAttribute(egnn_edge_kernel,
                         cudaFuncAttributeMaxDynamicSharedMemorySize, EDGE_SMEM_BYTES);
    cudaFuncSetAttribute(egnn_node_kernel,
                         cudaFuncAttributeMaxDynamicSharedMemorySize, NODE_SMEM_BYTES);

    egnn_detect_kernel<<<1, 256>>>((const long long*)ei, E);
    egnn_cvt_kernel<<<(2 * E + 255) / 256, 256>>>(ei, E);
    egnn_init_kernel<<<(N * 16 + 255) / 256, 256>>>(h, h_init, N);

    const int nTiles = (E + TILE_E - 1) / TILE_E;
    int eblocks = nTiles < 148 ? nTiles : 148;
    egnn_edge_kernel<<<eblocks, NTHREADS, EDGE_SMEM_BYTES>>>(
        pos, Wm1, bm1, Wm2, bm2, Wp1, bp1, Wp2, bp2, E, N);

    egnn_node_kernel<<<592, 128, NODE_SMEM_BYTES>>>(pos, Wh1, bh1, Wh2, bh2, out, N);
}